// round 13
// baseline (speedup 1.0000x reference)
#include <cuda_runtime.h>
#include <cuda_bf16.h>
#include <cuda_fp16.h>
#include <math.h>
#include <stdint.h>

typedef __half f16;

#define BB   2
#define CC   512
#define HWH  4096
#define ICI  256
#define SPAD 40

// int8 limb quantization constants
#define QA1   12.0f
#define QA2   0.00390625f
#define QS1   (QA1 / 127.0f)
#define QS2   (QA2 / 127.0f)
#define IQS1  (127.0f / QA1)
#define IQS2  (127.0f / QA2)
#define QSCALE (QS1 * QS2)

// ---------------- scratch ----------------
__device__ float d_mean[2 * BB * CC];
__device__ float d_istd[2 * BB * CC];

__device__ f16 d_xnT_hi[(size_t)BB * HWH * CC];
__device__ f16 d_xnT_lo[(size_t)BB * HWH * CC];
__device__ f16 d_snT_hi[(size_t)BB * HWH * CC];
__device__ f16 d_snT_lo[(size_t)BB * HWH * CC];
__device__ f16 d_fsT_hi[(size_t)BB * HWH * CC];
__device__ f16 d_fsT_lo[(size_t)BB * HWH * CC];

__device__ f16 d_thw_hi[ICI * CC], d_thw_lo[ICI * CC];
__device__ f16 d_phw_hi[ICI * CC], d_phw_lo[ICI * CC];
__device__ f16 d_gw_hi [ICI * CC], d_gw_lo [ICI * CC];
__device__ f16 d_Ww_hi [CC * ICI], d_Ww_lo [CC * ICI];

__device__ f16 d_thT_hi[(size_t)BB * HWH * ICI];
__device__ f16 d_phT_hi[(size_t)BB * HWH * ICI];
// int8 limb-concat buffers: theta = [hi | lo], phi = [lo | hi], row stride 2*ICI bytes
__device__ char d_thq[(size_t)BB * HWH * 2 * ICI];
__device__ char d_phq[(size_t)BB * HWH * 2 * ICI];

__device__ f16 d_gT_hi[(size_t)BB * ICI * HWH];
__device__ f16 d_gT_lo[(size_t)BB * ICI * HWH];

__device__ float d_G[(size_t)BB * HWH * HWH];

__device__ f16 d_P[(size_t)BB * HWH * HWH];

__device__ f16 d_y_hi[(size_t)BB * HWH * ICI];
__device__ f16 d_y_lo[(size_t)BB * HWH * ICI];

// ------------- stats -------------
__global__ void stats_kernel(const float* __restrict__ content,
                             const float* __restrict__ style) {
    int idx = blockIdx.x;
    int which = idx >> 10;
    int bc = idx & 1023;
    const float* src = (which == 0 ? content : style) + (size_t)bc * HWH;
    double s = 0.0, s2 = 0.0;
    for (int i = threadIdx.x; i < HWH; i += 256) {
        float v = src[i];
        s += v; s2 += (double)v * v;
    }
    __shared__ double sh1[256], sh2[256];
    sh1[threadIdx.x] = s; sh2[threadIdx.x] = s2;
    __syncthreads();
    for (int st = 128; st > 0; st >>= 1) {
        if (threadIdx.x < st) {
            sh1[threadIdx.x] += sh1[threadIdx.x + st];
            sh2[threadIdx.x] += sh2[threadIdx.x + st];
        }
        __syncthreads();
    }
    if (threadIdx.x == 0) {
        double mean = sh1[0] / (double)HWH;
        double var = (sh2[0] - (double)HWH * mean * mean) / (double)(HWH - 1);
        d_mean[idx] = (float)mean;
        d_istd[idx] = (float)(1.0 / sqrt(var + 1e-5));
    }
}

// ------ normalize + transpose + split (fp16) ------
__global__ void norm_split_T(const float* __restrict__ content,
                             const float* __restrict__ style,
                             const float* __restrict__ fusion) {
    int zz = blockIdx.z;
    int src = zz >> 1, b = zz & 1;
    const float* in;
    f16 *oh, *ol;
    if (src == 0)      { in = content; oh = d_xnT_hi; ol = d_xnT_lo; }
    else if (src == 1) { in = style;   oh = d_snT_hi; ol = d_snT_lo; }
    else               { in = fusion;  oh = d_fsT_hi; ol = d_fsT_lo; }
    in += (size_t)b * CC * HWH;
    oh += (size_t)b * HWH * CC;
    ol += (size_t)b * HWH * CC;

    int p0 = blockIdx.x * 32, c0 = blockIdx.y * 32;
    __shared__ float tile[32][33];
    int tx = threadIdx.x, ty = threadIdx.y;
    #pragma unroll
    for (int i = 0; i < 4; i++) {
        int c = c0 + ty + i * 8;
        float v = in[(size_t)c * HWH + p0 + tx];
        if (src < 2) {
            int mi = src * 1024 + b * 512 + c;
            v = (v - d_mean[mi]) * d_istd[mi];
        }
        tile[ty + i * 8][tx] = v;
    }
    __syncthreads();
    #pragma unroll
    for (int i = 0; i < 4; i++) {
        int p = p0 + ty + i * 8;
        int c = c0 + tx;
        float v = tile[tx][ty + i * 8];
        f16 h = __float2half_rn(v);
        size_t off = (size_t)p * CC + c;
        oh[off] = h;
        ol[off] = __float2half_rn(v - __half2float(h));
    }
}

// ------------- weight split (fp16) -------------
__global__ void weight_split(const float* __restrict__ tw, const float* __restrict__ pw,
                             const float* __restrict__ gw, const float* __restrict__ Ww) {
    int i = blockIdx.x * 256 + threadIdx.x;
    if (i >= ICI * CC) return;
    float v; f16 h;
    v = tw[i]; h = __float2half_rn(v); d_thw_hi[i] = h; d_thw_lo[i] = __float2half_rn(v - __half2float(h));
    v = pw[i]; h = __float2half_rn(v); d_phw_hi[i] = h; d_phw_lo[i] = __float2half_rn(v - __half2float(h));
    v = gw[i]; h = __float2half_rn(v); d_gw_hi[i]  = h; d_gw_lo[i]  = __float2half_rn(v - __half2float(h));
    v = Ww[i]; h = __float2half_rn(v); d_Ww_hi[i]  = h; d_Ww_lo[i]  = __float2half_rn(v - __half2float(h));
}

// ---------------- low-level helpers ----------------
__device__ __forceinline__ uint32_t smem_u32(const void* p) {
    uint32_t a;
    asm("{ .reg .u64 t; cvta.to.shared.u64 t, %1; cvt.u32.u64 %0, t; }"
        : "=r"(a) : "l"(p));
    return a;
}

__device__ __forceinline__ void cp16(uint32_t dst, const void* src) {
    asm volatile("cp.async.cg.shared.global [%0], [%1], 16;\n" :: "r"(dst), "l"(src));
}
__device__ __forceinline__ void cp_commit() { asm volatile("cp.async.commit_group;\n"); }
template<int N> __device__ __forceinline__ void cp_wait() {
    asm volatile("cp.async.wait_group %0;\n" :: "n"(N));
}

__device__ __forceinline__ void ldsm4(unsigned r[4], uint32_t addr) {
    asm volatile("ldmatrix.sync.aligned.m8n8.x4.shared.b16 {%0,%1,%2,%3}, [%4];"
                 : "=r"(r[0]), "=r"(r[1]), "=r"(r[2]), "=r"(r[3]) : "r"(addr));
}

__device__ __forceinline__ void mmaf16(float c[4], const unsigned a[4], const unsigned b[2]) {
    asm volatile(
        "mma.sync.aligned.m16n8k16.row.col.f32.f16.f16.f32 "
        "{%0,%1,%2,%3},{%4,%5,%6,%7},{%8,%9},{%0,%1,%2,%3};\n"
        : "+f"(c[0]), "+f"(c[1]), "+f"(c[2]), "+f"(c[3])
        : "r"(a[0]), "r"(a[1]), "r"(a[2]), "r"(a[3]), "r"(b[0]), "r"(b[1]));
}

__device__ __forceinline__ void mmas8(int c[4], const unsigned a[4], const unsigned b[2]) {
    asm volatile(
        "mma.sync.aligned.m16n8k32.row.col.s32.s8.s8.s32 "
        "{%0,%1,%2,%3},{%4,%5,%6,%7},{%8,%9},{%0,%1,%2,%3};\n"
        : "+r"(c[0]), "+r"(c[1]), "+r"(c[2]), "+r"(c[3])
        : "r"(a[0]), "r"(a[1]), "r"(a[2]), "r"(a[3]), "r"(b[0]), "r"(b[1]));
}

__device__ __forceinline__ int qclamp(int x) {
    return x < -127 ? -127 : (x > 127 ? 127 : x);
}

// ---------------- pipelined NT GEMM (fp16): NST stages ----------------
// OUTM: 0 fp32, 2 split fp16, 4 fp16 hi + int8 [hi|lo], 5 fp16 hi + int8 [lo|hi].
// BIASM: 0 none, 1 bias[row], 2 bias[col].
template<int ASPL, int BSPL, int OUTM, int BIASM, int WM_, int WN_, int BM, int BN, int NST>
__global__ __launch_bounds__(256)
void gemm_pl(const void* __restrict__ Ahi_, const void* __restrict__ Alo_,
             const void* __restrict__ Bhi_, const void* __restrict__ Blo_,
             const float* __restrict__ bias,
             void* __restrict__ C0, void* __restrict__ C1,
             int M, int N, int K,
             long long sA, long long sB, long long sC) {
    constexpr int NPA = 1 + ASPL, NPB = 1 + BSPL;
    constexpr int FM = BM / (16 * WM_), FN = BN / (8 * WN_);
    constexpr int ABYT = BM * SPAD * 2;
    constexpr int BBYT = BN * SPAD * 2;
    constexpr int SSB = NPA * ABYT + NPB * BBYT;
    extern __shared__ char sh[];
    const uint32_t sbase = smem_u32(sh);

    const int bz = blockIdx.z;
    const unsigned short* Ah = (const unsigned short*)Ahi_ + (size_t)bz * sA;
    const unsigned short* Al = (const unsigned short*)Alo_ + (size_t)bz * sA;
    const unsigned short* Bh = (const unsigned short*)Bhi_ + (size_t)bz * sB;
    const unsigned short* Bl = (const unsigned short*)Blo_ + (size_t)bz * sB;

    const int m0 = blockIdx.y * BM, n0 = blockIdx.x * BN;
    const int tid = threadIdx.x, warp = tid >> 5, lane = tid & 31;
    const int wm = warp / WN_, wn = warp % WN_;
    const int grp = lane >> 2, qid = lane & 3;

    const int r8 = lane & 7, mi = lane >> 3;
    const uint32_t aLane = (uint32_t)(((r8 + ((mi & 1) << 3)) * SPAD + ((mi >> 1) << 3)) * 2);
    const uint32_t bLane = (uint32_t)(((r8 + ((mi >> 1) << 3)) * SPAD + ((mi & 1) << 3)) * 2);

    float acc[FM][FN][4] = {};

    auto load_stage = [&](int st, int kt) {
        #pragma unroll
        for (int v = 0; v < NPA; v++) {
            const unsigned short* g = v ? Al : Ah;
            uint32_t base = sbase + st * SSB + v * ABYT;
            #pragma unroll
            for (int cid = tid; cid < BM * 4; cid += 256) {
                int row = cid >> 2, seg = cid & 3;
                cp16(base + (uint32_t)((row * SPAD + seg * 8) * 2),
                     g + (size_t)(m0 + row) * K + kt + seg * 8);
            }
        }
        #pragma unroll
        for (int v = 0; v < NPB; v++) {
            const unsigned short* g = v ? Bl : Bh;
            uint32_t base = sbase + st * SSB + NPA * ABYT + v * BBYT;
            #pragma unroll
            for (int cid = tid; cid < BN * 4; cid += 256) {
                int row = cid >> 2, seg = cid & 3;
                cp16(base + (uint32_t)((row * SPAD + seg * 8) * 2),
                     g + (size_t)(n0 + row) * K + kt + seg * 8);
            }
        }
    };

    const int KT = K / 32;
    #pragma unroll
    for (int p = 0; p < NST - 1; p++) {
        if (p < KT) { load_stage(p, p * 32); cp_commit(); }
    }

    for (int it = 0; it < KT; ++it) {
        const int st = it % NST;
        if (KT - 1 - it >= NST - 2) cp_wait<(NST >= 2 ? NST - 2 : 0)>();
        else                        cp_wait<0>();
        __syncthreads();

        const int nx = it + NST - 1;
        if (nx < KT) { load_stage(nx % NST, nx * 32); cp_commit(); }

        const uint32_t sA0 = sbase + st * SSB;
        const uint32_t sA1 = sA0 + ABYT;
        const uint32_t sB0 = sbase + st * SSB + NPA * ABYT;
        const uint32_t sB1 = sB0 + BBYT;

        #pragma unroll
        for (int kk = 0; kk < 2; kk++) {
            const uint32_t koff = kk * 32;
            unsigned a[FM][4], b0[FN][2], b1[FN][2];
            #pragma unroll
            for (int nn2 = 0; nn2 < FN / 2; nn2++) {
                uint32_t boff = bLane + (uint32_t)((wn * FN * 8 + nn2 * 16) * SPAD * 2) + koff;
                ldsm4(&b0[2 * nn2][0], sB0 + boff);
                if (BSPL) ldsm4(&b1[2 * nn2][0], sB1 + boff);
            }
            #pragma unroll
            for (int mm = 0; mm < FM; mm++) {
                uint32_t aoff = aLane + (uint32_t)((wm * FM * 16 + mm * 16) * SPAD * 2) + koff;
                ldsm4(a[mm], sA0 + aoff);
            }
            #pragma unroll
            for (int mm = 0; mm < FM; mm++)
                #pragma unroll
                for (int nn = 0; nn < FN; nn++) {
                    mmaf16(acc[mm][nn], a[mm], b0[nn]);
                    if (BSPL) mmaf16(acc[mm][nn], a[mm], b1[nn]);
                }
            if (ASPL) {
                #pragma unroll
                for (int mm = 0; mm < FM; mm++) {
                    uint32_t aoff = aLane + (uint32_t)((wm * FM * 16 + mm * 16) * SPAD * 2) + koff;
                    ldsm4(a[mm], sA1 + aoff);
                }
                #pragma unroll
                for (int mm = 0; mm < FM; mm++)
                    #pragma unroll
                    for (int nn = 0; nn < FN; nn++)
                        mmaf16(acc[mm][nn], a[mm], b0[nn]);
            }
        }
    }

    #pragma unroll
    for (int mm = 0; mm < FM; mm++) {
        #pragma unroll
        for (int nn = 0; nn < FN; nn++) {
            #pragma unroll
            for (int half = 0; half < 2; half++) {
                int row = m0 + wm * (FM * 16) + mm * 16 + grp + half * 8;
                int col = n0 + wn * (FN * 8) + nn * 8 + qid * 2;
                float v0 = acc[mm][nn][half * 2 + 0];
                float v1 = acc[mm][nn][half * 2 + 1];
                if (BIASM == 1) { float bb = bias[row]; v0 += bb; v1 += bb; }
                if (BIASM == 2) { v0 += bias[col]; v1 += bias[col + 1]; }
                size_t off = (size_t)bz * sC + (size_t)row * N + col;
                if (OUTM == 0) {
                    float2 p; p.x = v0; p.y = v1;
                    *(float2*)((float*)C0 + off) = p;
                } else if (OUTM == 2) {
                    f16 h0 = __float2half_rn(v0), h1 = __float2half_rn(v1);
                    f16 l0 = __float2half_rn(v0 - __half2float(h0));
                    f16 l1 = __float2half_rn(v1 - __half2float(h1));
                    __half2 hp; hp.x = h0; hp.y = h1;
                    __half2 lp; lp.x = l0; lp.y = l1;
                    *(__half2*)((f16*)C0 + off) = hp;
                    *(__half2*)((f16*)C1 + off) = lp;
                } else {  // OUTM 4 / 5: fp16 hi + int8 limb-concat
                    f16 h0 = __float2half_rn(v0), h1 = __float2half_rn(v1);
                    __half2 hp; hp.x = h0; hp.y = h1;
                    *(__half2*)((f16*)C0 + off) = hp;
                    float hf0 = __half2float(h0), hf1 = __half2float(h1);
                    int qh0 = qclamp(__float2int_rn(hf0 * IQS1));
                    int qh1 = qclamp(__float2int_rn(hf1 * IQS1));
                    int ql0 = qclamp(__float2int_rn((v0 - hf0) * IQS2));
                    int ql1 = qclamp(__float2int_rn((v1 - hf1) * IQS2));
                    short hipk = (short)((qh0 & 0xFF) | ((qh1 & 0xFF) << 8));
                    short lopk = (short)((ql0 & 0xFF) | ((ql1 & 0xFF) << 8));
                    char* cq = (char*)C1;
                    size_t qb = (size_t)bz * 2 * sC + (size_t)row * (2 * N) + col;
                    if (OUTM == 4) {
                        *(short*)(cq + qb) = hipk;
                        *(short*)(cq + qb + N) = lopk;
                    } else {
                        *(short*)(cq + qb) = lopk;
                        *(short*)(cq + qb + N) = hipk;
                    }
                }
            }
        }
    }
}

// ---------------- G kernel: fp16 hi*hi + int8 cross-term correction ----------------
// G = thH*phH^T (fp16, K=256) + QSCALE * [thq]*[phq]^T (s8, K=512 bytes)
// thq = [th_hi_q | th_lo_q], phq = [ph_lo_q | ph_hi_q] so the s8 GEMM = hi*lo + lo*hi.
__global__ __launch_bounds__(256)
void gemm_G(const unsigned short* __restrict__ thH, const unsigned short* __restrict__ phH,
            const unsigned short* __restrict__ thQ, const unsigned short* __restrict__ phQ,
            float* __restrict__ C) {
    constexpr int FM = 4, FN = 4;
    constexpr int ABYT = 128 * SPAD * 2, SSB = 2 * ABYT;
    extern __shared__ char sh[];
    const uint32_t sbase = smem_u32(sh);
    const int bz = blockIdx.z;
    const size_t bo = (size_t)bz * HWH * ICI;   // b16 units (512 bytes/row for both)
    thH += bo; phH += bo; thQ += bo; phQ += bo;
    const int m0 = blockIdx.y * 128, n0 = blockIdx.x * 128;
    const int tid = threadIdx.x, warp = tid >> 5, lane = tid & 31;
    const int wm = warp >> 2, wn = warp & 3;   // WM=2, WN=4
    const int grp = lane >> 2, qid = lane & 3;
    const int r8 = lane & 7, mi = lane >> 3;
    const uint32_t aLane = (uint32_t)(((r8 + ((mi & 1) << 3)) * SPAD + ((mi >> 1) << 3)) * 2);
    const uint32_t bLane = (uint32_t)(((r8 + ((mi >> 1) << 3)) * SPAD + ((mi & 1) << 3)) * 2);

    union { int i[FM][FN][4]; float f[FM][FN][4]; } acc;
    #pragma unroll
    for (int mm = 0; mm < FM; mm++)
        #pragma unroll
        for (int nn = 0; nn < FN; nn++)
            #pragma unroll
            for (int r = 0; r < 4; r++) acc.i[mm][nn][r] = 0;

    auto load_stage = [&](int st, int itg) {
        const unsigned short* A = (itg < 8) ? thQ : thH;
        const unsigned short* B = (itg < 8) ? phQ : phH;
        const int kt = (itg & 7) * 32;
        uint32_t baseA = sbase + st * SSB;
        #pragma unroll
        for (int cid = tid; cid < 128 * 4; cid += 256) {
            int row = cid >> 2, seg = cid & 3;
            cp16(baseA + (uint32_t)((row * SPAD + seg * 8) * 2),
                 A + (size_t)(m0 + row) * 256 + kt + seg * 8);
        }
        uint32_t baseB = sbase + st * SSB + ABYT;
        #pragma unroll
        for (int cid = tid; cid < 128 * 4; cid += 256) {
            int row = cid >> 2, seg = cid & 3;
            cp16(baseB + (uint32_t)((row * SPAD + seg * 8) * 2),
                 B + (size_t)(n0 + row) * 256 + kt + seg * 8);
        }
    };

    load_stage(0, 0); cp_commit();
    for (int it = 0; it < 16; ++it) {
        const int st = it & 1;
        cp_wait<0>();
        __syncthreads();
        if (it + 1 < 16) { load_stage(st ^ 1, it + 1); cp_commit(); }

        const uint32_t sA0 = sbase + st * SSB;
        const uint32_t sB0 = sA0 + ABYT;
        #pragma unroll
        for (int kk = 0; kk < 2; kk++) {
            const uint32_t koff = kk * 32;
            unsigned a[FM][4], b0[FN][2];
            #pragma unroll
            for (int nn2 = 0; nn2 < FN / 2; nn2++) {
                uint32_t boff = bLane + (uint32_t)((wn * 32 + nn2 * 16) * SPAD * 2) + koff;
                ldsm4(&b0[2 * nn2][0], sB0 + boff);
            }
            #pragma unroll
            for (int mm = 0; mm < FM; mm++) {
                uint32_t aoff = aLane + (uint32_t)((wm * 64 + mm * 16) * SPAD * 2) + koff;
                ldsm4(a[mm], sA0 + aoff);
            }
            if (it < 8) {
                #pragma unroll
                for (int mm = 0; mm < FM; mm++)
                    #pragma unroll
                    for (int nn = 0; nn < FN; nn++)
                        mmas8(acc.i[mm][nn], a[mm], b0[nn]);
            } else {
                #pragma unroll
                for (int mm = 0; mm < FM; mm++)
                    #pragma unroll
                    for (int nn = 0; nn < FN; nn++)
                        mmaf16(acc.f[mm][nn], a[mm], b0[nn]);
            }
        }
        if (it == 7) {
            #pragma unroll
            for (int mm = 0; mm < FM; mm++)
                #pragma unroll
                for (int nn = 0; nn < FN; nn++)
                    #pragma unroll
                    for (int r = 0; r < 4; r++)
                        acc.f[mm][nn][r] = (float)acc.i[mm][nn][r] * QSCALE;
        }
    }

    #pragma unroll
    for (int mm = 0; mm < FM; mm++) {
        #pragma unroll
        for (int nn = 0; nn < FN; nn++) {
            #pragma unroll
            for (int half = 0; half < 2; half++) {
                int row = m0 + wm * 64 + mm * 16 + grp + half * 8;
                int col = n0 + wn * 32 + nn * 8 + qid * 2;
                float2 p;
                p.x = acc.f[mm][nn][half * 2 + 0];
                p.y = acc.f[mm][nn][half * 2 + 1];
                *(float2*)(C + (size_t)bz * HWH * HWH + (size_t)row * HWH + col) = p;
            }
        }
    }
}

// ------- fused f-assembly + softmax, register-resident, P -> fp16 -------
__device__ __forceinline__ int refl(int i) {
    return i < 0 ? -i : (i > 63 ? 126 - i : i);
}

__global__ __launch_bounds__(256)
void attn_softmax_kernel(const float* __restrict__ scale) {
    const int l = blockIdx.x;
    const int b = blockIdx.y;
    const int tid = threadIdx.x;
    const int il = l >> 6, jl = l & 63;

    __shared__ float red[256];

    const float* Gb = d_G + (size_t)b * HWH * HWH;
    const float* gr[9];
    float s2[9];
    #pragma unroll
    for (int k = 0; k < 9; k++) {
        int di = k / 3, dj = k % 3;
        gr[k] = Gb + (size_t)(refl(il + di - 1) * 64 + refl(jl + dj - 1)) * HWH;
        float s = scale[k];
        s2[k] = s * s;
    }

    float v[16];
    float mx = -3.4e38f;
    #pragma unroll
    for (int i = 0; i < 16; i++) {
        int m = tid + i * 256;
        int im = m >> 6, jm = m & 63;
        float acc = 0.f;
        #pragma unroll
        for (int di = 0; di < 3; di++) {
            int ci = refl(im + di - 1) * 64;
            #pragma unroll
            for (int dj = 0; dj < 3; dj++)
                acc += s2[di * 3 + dj] * gr[di * 3 + dj][ci + refl(jm + dj - 1)];
        }
        v[i] = acc;
        mx = fmaxf(mx, acc);
    }
    red[tid] = mx; __syncthreads();
    for (int st = 128; st > 0; st >>= 1) {
        if (tid < st) red[tid] = fmaxf(red[tid], red[tid + st]);
        __syncthreads();
    }
    mx = red[0];
    __syncthreads();

    float sum = 0.f;
    #pragma unroll
    for (int i = 0; i < 16; i++) {
        v[i] = __expf(v[i] - mx);
        sum += v[i];
    }
    red[tid] = sum; __syncthreads();
    for (int st = 128; st > 0; st >>= 1) {
        if (tid < st) red[tid] += red[tid + st];
        __syncthreads();
    }
    float inv = 1.f / red[0];

    f16* pr = d_P + ((size_t)b * HWH + l) * HWH;
    #pragma unroll
    for (int i = 0; i < 16; i++)
        pr[tid + i * 256] = __float2half_rn(v[i] * inv);
}

// ---------------- host ----------------
#define SYM(p, s) do { void* _t; cudaGetSymbolAddress(&_t, s); p = (decltype(p))_t; } while (0)

#define LAUNCH_GEMM(ASPL, BSPL, OUTM, BIASM, WM, WN, BM, BN, NST, Ah, Al, Bh, Bl, bias, C0, C1, M, N, K, sa, sb, sc) \
    do { \
        auto kfn = gemm_pl<ASPL, BSPL, OUTM, BIASM, WM, WN, BM, BN, NST>; \
        int smemB = (NST) * ((1 + ASPL) * (BM) + (1 + BSPL) * (BN)) * SPAD * 2; \
        cudaFuncSetAttribute(kfn, cudaFuncAttributeMaxDynamicSharedMemorySize, smemB); \
        kfn<<<dim3((N) / (BN), (M) / (BM), BB), 256, smemB>>>( \
            Ah, Al, Bh, Bl, bias, C0, C1, M, N, K, sa, sb, sc); \
    } while (0)

extern "C" void kernel_launch(void* const* d_in, const int* in_sizes, int n_in,
                              void* d_out, int out_size) {
    (void)in_sizes; (void)n_in; (void)out_size;
    const float* content = (const float*)d_in[0];
    const float* style   = (const float*)d_in[1];
    const float* fusion  = (const float*)d_in[2];
    const float* theta_b = (const float*)d_in[4];
    const float* phi_b   = (const float*)d_in[6];
    const float* g_b     = (const float*)d_in[8];
    const float* W_b     = (const float*)d_in[10];
    const float* scale   = (const float*)d_in[11];
    float* out = (float*)d_out;

    f16 *xnT_hi, *xnT_lo, *snT_hi, *snT_lo, *fsT_hi, *fsT_lo;
    f16 *thw_hi, *thw_lo, *phw_hi, *phw_lo, *gw_hi, *gw_lo, *Ww_hi, *Ww_lo;
    f16 *thT_hi, *phT_hi;
    char *thq, *phq;
    f16 *gT_hi, *gT_lo, *Pp;
    f16 *y_hi, *y_lo;
    float* Gp;
    SYM(xnT_hi, d_xnT_hi); SYM(xnT_lo, d_xnT_lo);
    SYM(snT_hi, d_snT_hi); SYM(snT_lo, d_snT_lo);
    SYM(fsT_hi, d_fsT_hi); SYM(fsT_lo, d_fsT_lo);
    SYM(thw_hi, d_thw_hi); SYM(thw_lo, d_thw_lo);
    SYM(phw_hi, d_phw_hi); SYM(phw_lo, d_phw_lo);
    SYM(gw_hi,  d_gw_hi);  SYM(gw_lo,  d_gw_lo);
    SYM(Ww_hi,  d_Ww_hi);  SYM(Ww_lo,  d_Ww_lo);
    SYM(thT_hi, d_thT_hi); SYM(phT_hi, d_phT_hi);
    SYM(thq,    d_thq);    SYM(phq,    d_phq);
    SYM(gT_hi,  d_gT_hi);  SYM(gT_lo,  d_gT_lo);
    SYM(Pp,     d_P);
    SYM(y_hi,   d_y_hi);   SYM(y_lo,   d_y_lo);
    SYM(Gp,     d_G);

    // 1) instance-norm stats
    stats_kernel<<<2 * BB * CC, 256>>>(content, style);
    // 2) normalize + transpose + split (fp16)
    norm_split_T<<<dim3(HWH / 32, CC / 32, 3 * BB), dim3(32, 8)>>>(content, style, fusion);
    // 3) weight splits (fp16)
    weight_split<<<(ICI * CC) / 256, 256>>>((const float*)d_in[3], (const float*)d_in[5],
                                            (const float*)d_in[7], (const float*)d_in[9]);

    // 4) theta_xT : M=4096, N=256, K=512, 3-pass; out = fp16 hi + int8 [hi|lo]
    LAUNCH_GEMM(1, 1, 4, 2, 4, 2, 128, 64, 3,
                xnT_hi, xnT_lo, thw_hi, thw_lo, theta_b, thT_hi, thq,
                HWH, ICI, CC, (long long)HWH * CC, 0LL, (long long)HWH * ICI);

    // 5) phi_sT : out = fp16 hi + int8 [lo|hi]
    LAUNCH_GEMM(1, 1, 5, 2, 4, 2, 128, 64, 3,
                snT_hi, snT_lo, phw_hi, phw_lo, phi_b, phT_hi, phq,
                HWH, ICI, CC, (long long)HWH * CC, 0LL, (long long)HWH * ICI);

    // 6) g_sT : M=256, N=4096, K=512 -> split fp16 (3-pass, unchanged)
    LAUNCH_GEMM(1, 1, 2, 1, 4, 2, 128, 64, 3,
                gw_hi, gw_lo, fsT_hi, fsT_lo, g_b, gT_hi, gT_lo,
                ICI, HWH, CC, 0LL, (long long)HWH * CC, (long long)ICI * HWH);

    // 7) G : fp16 hi*hi + int8 cross-term correction (2 effective units)
    {
        int smemB = 2 * 2 * 128 * SPAD * 2;
        cudaFuncSetAttribute(gemm_G, cudaFuncAttributeMaxDynamicSharedMemorySize, smemB);
        gemm_G<<<dim3(32, 32, BB), 256, smemB>>>(
            (const unsigned short*)thT_hi, (const unsigned short*)phT_hi,
            (const unsigned short*)thq, (const unsigned short*)phq, Gp);
    }

    // 8) gather + softmax -> P (fp16)
    attn_softmax_kernel<<<dim3(HWH, BB), 256>>>(scale);

    // 9) y = P @ g_s : single pass (P fp16 x g_hi fp16), grid 256
    LAUNCH_GEMM(0, 0, 2, 0, 4, 2, 128, 64, 3,
                Pp, Pp, gT_hi, gT_hi, (const float*)nullptr, y_hi, y_lo,
                HWH, ICI, HWH, (long long)HWH * HWH, (long long)ICI * HWH, (long long)HWH * ICI);

    // 10) out = W_w @ y^T + W_b : M=512, N=4096, K=256 -> fp32, 3-pass
    LAUNCH_GEMM(1, 1, 0, 1, 2, 4, 128, 128, 2,
                Ww_hi, Ww_lo, y_hi, y_lo, W_b, out, (void*)nullptr,
                CC, HWH, ICI, 0LL, (long long)HWH * ICI, (long long)CC * HWH);
}

// round 14
// speedup vs baseline: 1.2381x; 1.2381x over previous
#include <cuda_runtime.h>
#include <cuda_bf16.h>
#include <cuda_fp16.h>
#include <math.h>
#include <stdint.h>

typedef __half f16;

#define BB   2
#define CC   512
#define HWH  4096
#define ICI  256
#define SPAD 40

// ---------------- scratch (all operands fp16 split) ----------------
__device__ float d_mean[2 * BB * CC];
__device__ float d_istd[2 * BB * CC];

__device__ f16 d_xnT_hi[(size_t)BB * HWH * CC];
__device__ f16 d_xnT_lo[(size_t)BB * HWH * CC];
__device__ f16 d_snT_hi[(size_t)BB * HWH * CC];
__device__ f16 d_snT_lo[(size_t)BB * HWH * CC];
__device__ f16 d_fsT_hi[(size_t)BB * HWH * CC];
__device__ f16 d_fsT_lo[(size_t)BB * HWH * CC];

__device__ f16 d_thw_hi[ICI * CC], d_thw_lo[ICI * CC];
__device__ f16 d_phw_hi[ICI * CC], d_phw_lo[ICI * CC];
__device__ f16 d_gw_hi [ICI * CC], d_gw_lo [ICI * CC];
__device__ f16 d_Ww_hi [CC * ICI], d_Ww_lo [CC * ICI];

__device__ f16 d_thT_hi[(size_t)BB * HWH * ICI];
__device__ f16 d_thT_lo[(size_t)BB * HWH * ICI];
__device__ f16 d_phT_hi[(size_t)BB * HWH * ICI];
__device__ f16 d_phT_lo[(size_t)BB * HWH * ICI];

__device__ f16 d_gT_hi[(size_t)BB * ICI * HWH];
__device__ f16 d_gT_lo[(size_t)BB * ICI * HWH];

__device__ float d_G[(size_t)BB * HWH * HWH];

__device__ f16 d_P[(size_t)BB * HWH * HWH];

__device__ f16 d_y_hi[(size_t)BB * HWH * ICI];
__device__ f16 d_y_lo[(size_t)BB * HWH * ICI];

// ------------- stats -------------
__global__ void stats_kernel(const float* __restrict__ content,
                             const float* __restrict__ style) {
    int idx = blockIdx.x;
    int which = idx >> 10;
    int bc = idx & 1023;
    const float* src = (which == 0 ? content : style) + (size_t)bc * HWH;
    double s = 0.0, s2 = 0.0;
    for (int i = threadIdx.x; i < HWH; i += 256) {
        float v = src[i];
        s += v; s2 += (double)v * v;
    }
    __shared__ double sh1[256], sh2[256];
    sh1[threadIdx.x] = s; sh2[threadIdx.x] = s2;
    __syncthreads();
    for (int st = 128; st > 0; st >>= 1) {
        if (threadIdx.x < st) {
            sh1[threadIdx.x] += sh1[threadIdx.x + st];
            sh2[threadIdx.x] += sh2[threadIdx.x + st];
        }
        __syncthreads();
    }
    if (threadIdx.x == 0) {
        double mean = sh1[0] / (double)HWH;
        double var = (sh2[0] - (double)HWH * mean * mean) / (double)(HWH - 1);
        d_mean[idx] = (float)mean;
        d_istd[idx] = (float)(1.0 / sqrt(var + 1e-5));
    }
}

// ------ normalize + transpose + split (fp16) ------
__global__ void norm_split_T(const float* __restrict__ content,
                             const float* __restrict__ style,
                             const float* __restrict__ fusion) {
    int zz = blockIdx.z;
    int src = zz >> 1, b = zz & 1;
    const float* in;
    f16 *oh, *ol;
    if (src == 0)      { in = content; oh = d_xnT_hi; ol = d_xnT_lo; }
    else if (src == 1) { in = style;   oh = d_snT_hi; ol = d_snT_lo; }
    else               { in = fusion;  oh = d_fsT_hi; ol = d_fsT_lo; }
    in += (size_t)b * CC * HWH;
    oh += (size_t)b * HWH * CC;
    ol += (size_t)b * HWH * CC;

    int p0 = blockIdx.x * 32, c0 = blockIdx.y * 32;
    __shared__ float tile[32][33];
    int tx = threadIdx.x, ty = threadIdx.y;
    #pragma unroll
    for (int i = 0; i < 4; i++) {
        int c = c0 + ty + i * 8;
        float v = in[(size_t)c * HWH + p0 + tx];
        if (src < 2) {
            int mi = src * 1024 + b * 512 + c;
            v = (v - d_mean[mi]) * d_istd[mi];
        }
        tile[ty + i * 8][tx] = v;
    }
    __syncthreads();
    #pragma unroll
    for (int i = 0; i < 4; i++) {
        int p = p0 + ty + i * 8;
        int c = c0 + tx;
        float v = tile[tx][ty + i * 8];
        f16 h = __float2half_rn(v);
        size_t off = (size_t)p * CC + c;
        oh[off] = h;
        ol[off] = __float2half_rn(v - __half2float(h));
    }
}

// ------------- weight split (fp16) -------------
__global__ void weight_split(const float* __restrict__ tw, const float* __restrict__ pw,
                             const float* __restrict__ gw, const float* __restrict__ Ww) {
    int i = blockIdx.x * 256 + threadIdx.x;
    if (i >= ICI * CC) return;
    float v; f16 h;
    v = tw[i]; h = __float2half_rn(v); d_thw_hi[i] = h; d_thw_lo[i] = __float2half_rn(v - __half2float(h));
    v = pw[i]; h = __float2half_rn(v); d_phw_hi[i] = h; d_phw_lo[i] = __float2half_rn(v - __half2float(h));
    v = gw[i]; h = __float2half_rn(v); d_gw_hi[i]  = h; d_gw_lo[i]  = __float2half_rn(v - __half2float(h));
    v = Ww[i]; h = __float2half_rn(v); d_Ww_hi[i]  = h; d_Ww_lo[i]  = __float2half_rn(v - __half2float(h));
}

// ---------------- low-level helpers ----------------
__device__ __forceinline__ uint32_t smem_u32(const void* p) {
    uint32_t a;
    asm("{ .reg .u64 t; cvta.to.shared.u64 t, %1; cvt.u32.u64 %0, t; }"
        : "=r"(a) : "l"(p));
    return a;
}

__device__ __forceinline__ void cp16(uint32_t dst, const void* src) {
    asm volatile("cp.async.cg.shared.global [%0], [%1], 16;\n" :: "r"(dst), "l"(src));
}
__device__ __forceinline__ void cp_commit() { asm volatile("cp.async.commit_group;\n"); }
template<int N> __device__ __forceinline__ void cp_wait() {
    asm volatile("cp.async.wait_group %0;\n" :: "n"(N));
}

__device__ __forceinline__ void ldsm4(unsigned r[4], uint32_t addr) {
    asm volatile("ldmatrix.sync.aligned.m8n8.x4.shared.b16 {%0,%1,%2,%3}, [%4];"
                 : "=r"(r[0]), "=r"(r[1]), "=r"(r[2]), "=r"(r[3]) : "r"(addr));
}

__device__ __forceinline__ void mmaf16(float c[4], const unsigned a[4], const unsigned b[2]) {
    asm volatile(
        "mma.sync.aligned.m16n8k16.row.col.f32.f16.f16.f32 "
        "{%0,%1,%2,%3},{%4,%5,%6,%7},{%8,%9},{%0,%1,%2,%3};\n"
        : "+f"(c[0]), "+f"(c[1]), "+f"(c[2]), "+f"(c[3])
        : "r"(a[0]), "r"(a[1]), "r"(a[2]), "r"(a[3]), "r"(b[0]), "r"(b[1]));
}

// ---------------- pipelined NT GEMM (fp16): NST stages, fissioned MMA passes ----------------
// C[M][N] = sum_k A[m,k]*B[n,k]; A versions = 1+ASPL (hi[,lo]), B = 1+BSPL.
// Passes fully fissioned: all-acc b0 pass, then all-acc b1 pass, then all-acc lo pass,
// so same-accumulator MMA reuse distance is FM*FN (8) instructions.
// OUTM: 0 fp32, 2 split fp16. BIASM: 0 none, 1 bias[row], 2 bias[col].
template<int ASPL, int BSPL, int OUTM, int BIASM, int WM_, int WN_, int BM, int BN, int NST>
__global__ __launch_bounds__(256)
void gemm_pl(const void* __restrict__ Ahi_, const void* __restrict__ Alo_,
             const void* __restrict__ Bhi_, const void* __restrict__ Blo_,
             const float* __restrict__ bias,
             void* __restrict__ C0, void* __restrict__ C1,
             int M, int N, int K,
             long long sA, long long sB, long long sC) {
    constexpr int NPA = 1 + ASPL, NPB = 1 + BSPL;
    constexpr int FM = BM / (16 * WM_), FN = BN / (8 * WN_);
    constexpr int ABYT = BM * SPAD * 2;
    constexpr int BBYT = BN * SPAD * 2;
    constexpr int SSB = NPA * ABYT + NPB * BBYT;
    extern __shared__ char sh[];
    const uint32_t sbase = smem_u32(sh);

    const int bz = blockIdx.z;
    const unsigned short* Ah = (const unsigned short*)Ahi_ + (size_t)bz * sA;
    const unsigned short* Al = (const unsigned short*)Alo_ + (size_t)bz * sA;
    const unsigned short* Bh = (const unsigned short*)Bhi_ + (size_t)bz * sB;
    const unsigned short* Bl = (const unsigned short*)Blo_ + (size_t)bz * sB;

    const int m0 = blockIdx.y * BM, n0 = blockIdx.x * BN;
    const int tid = threadIdx.x, warp = tid >> 5, lane = tid & 31;
    const int wm = warp / WN_, wn = warp % WN_;
    const int grp = lane >> 2, qid = lane & 3;

    const int r8 = lane & 7, mi = lane >> 3;
    const uint32_t aLane = (uint32_t)(((r8 + ((mi & 1) << 3)) * SPAD + ((mi >> 1) << 3)) * 2);
    const uint32_t bLane = (uint32_t)(((r8 + ((mi >> 1) << 3)) * SPAD + ((mi & 1) << 3)) * 2);

    float acc[FM][FN][4] = {};

    auto load_stage = [&](int st, int kt) {
        #pragma unroll
        for (int v = 0; v < NPA; v++) {
            const unsigned short* g = v ? Al : Ah;
            uint32_t base = sbase + st * SSB + v * ABYT;
            #pragma unroll
            for (int cid = tid; cid < BM * 4; cid += 256) {
                int row = cid >> 2, seg = cid & 3;
                cp16(base + (uint32_t)((row * SPAD + seg * 8) * 2),
                     g + (size_t)(m0 + row) * K + kt + seg * 8);
            }
        }
        #pragma unroll
        for (int v = 0; v < NPB; v++) {
            const unsigned short* g = v ? Bl : Bh;
            uint32_t base = sbase + st * SSB + NPA * ABYT + v * BBYT;
            #pragma unroll
            for (int cid = tid; cid < BN * 4; cid += 256) {
                int row = cid >> 2, seg = cid & 3;
                cp16(base + (uint32_t)((row * SPAD + seg * 8) * 2),
                     g + (size_t)(n0 + row) * K + kt + seg * 8);
            }
        }
    };

    const int KT = K / 32;
    #pragma unroll
    for (int p = 0; p < NST - 1; p++) {
        if (p < KT) { load_stage(p, p * 32); cp_commit(); }
    }

    for (int it = 0; it < KT; ++it) {
        const int st = it % NST;
        if (KT - 1 - it >= NST - 2) cp_wait<(NST >= 2 ? NST - 2 : 0)>();
        else                        cp_wait<0>();
        __syncthreads();

        const int nx = it + NST - 1;
        if (nx < KT) { load_stage(nx % NST, nx * 32); cp_commit(); }

        const uint32_t sA0 = sbase + st * SSB;
        const uint32_t sA1 = sA0 + ABYT;
        const uint32_t sB0 = sbase + st * SSB + NPA * ABYT;
        const uint32_t sB1 = sB0 + BBYT;

        #pragma unroll
        for (int kk = 0; kk < 2; kk++) {
            const uint32_t koff = kk * 32;
            unsigned a[FM][4], a2[FM][4], b0[FN][2], b1[FN][2];
            #pragma unroll
            for (int nn2 = 0; nn2 < FN / 2; nn2++) {
                uint32_t boff = bLane + (uint32_t)((wn * FN * 8 + nn2 * 16) * SPAD * 2) + koff;
                ldsm4(&b0[2 * nn2][0], sB0 + boff);
                if (BSPL) ldsm4(&b1[2 * nn2][0], sB1 + boff);
            }
            #pragma unroll
            for (int mm = 0; mm < FM; mm++) {
                uint32_t aoff = aLane + (uint32_t)((wm * FM * 16 + mm * 16) * SPAD * 2) + koff;
                ldsm4(a[mm], sA0 + aoff);
                if (ASPL) ldsm4(a2[mm], sA1 + aoff);
            }
            // pass 1: hi*hi — 8 independent accumulator chains
            #pragma unroll
            for (int mm = 0; mm < FM; mm++)
                #pragma unroll
                for (int nn = 0; nn < FN; nn++)
                    mmaf16(acc[mm][nn], a[mm], b0[nn]);
            // pass 2: hi*lo
            if (BSPL) {
                #pragma unroll
                for (int mm = 0; mm < FM; mm++)
                    #pragma unroll
                    for (int nn = 0; nn < FN; nn++)
                        mmaf16(acc[mm][nn], a[mm], b1[nn]);
            }
            // pass 3: lo*hi
            if (ASPL) {
                #pragma unroll
                for (int mm = 0; mm < FM; mm++)
                    #pragma unroll
                    for (int nn = 0; nn < FN; nn++)
                        mmaf16(acc[mm][nn], a2[mm], b0[nn]);
            }
        }
    }

    #pragma unroll
    for (int mm = 0; mm < FM; mm++) {
        #pragma unroll
        for (int nn = 0; nn < FN; nn++) {
            #pragma unroll
            for (int half = 0; half < 2; half++) {
                int row = m0 + wm * (FM * 16) + mm * 16 + grp + half * 8;
                int col = n0 + wn * (FN * 8) + nn * 8 + qid * 2;
                float v0 = acc[mm][nn][half * 2 + 0];
                float v1 = acc[mm][nn][half * 2 + 1];
                if (BIASM == 1) { float bb = bias[row]; v0 += bb; v1 += bb; }
                if (BIASM == 2) { v0 += bias[col]; v1 += bias[col + 1]; }
                size_t off = (size_t)bz * sC + (size_t)row * N + col;
                if (OUTM == 0) {
                    float2 p; p.x = v0; p.y = v1;
                    *(float2*)((float*)C0 + off) = p;
                } else {
                    f16 h0 = __float2half_rn(v0), h1 = __float2half_rn(v1);
                    f16 l0 = __float2half_rn(v0 - __half2float(h0));
                    f16 l1 = __float2half_rn(v1 - __half2float(h1));
                    __half2 hp; hp.x = h0; hp.y = h1;
                    __half2 lp; lp.x = l0; lp.y = l1;
                    *(__half2*)((f16*)C0 + off) = hp;
                    *(__half2*)((f16*)C1 + off) = lp;
                }
            }
        }
    }
}

// ------- fused f-assembly + softmax, 2x2 l-patch per block, P -> fp16 -------
__device__ __forceinline__ int refl(int i) {
    return i < 0 ? -i : (i > 63 ? 126 - i : i);
}

__global__ __launch_bounds__(256)
void attn_softmax_kernel(const float* __restrict__ scale) {
    const int bx = blockIdx.x;          // 0..1023 : 32x32 patch grid
    const int b = blockIdx.y;
    const int pil = bx >> 5, pjl = bx & 31;
    const int tid = threadIdx.x;

    __shared__ float red[256];

    const float* Gb = d_G + (size_t)b * HWH * HWH;
    float s2[9];
    #pragma unroll
    for (int k = 0; k < 9; k++) {
        float s = scale[k];
        s2[k] = s * s;
    }

    #pragma unroll
    for (int rr = 0; rr < 4; rr++) {
        const int il = 2 * pil + (rr >> 1);
        const int jl = 2 * pjl + (rr & 1);
        const int l = il * 64 + jl;

        const float* gr[9];
        #pragma unroll
        for (int k = 0; k < 9; k++) {
            int di = k / 3, dj = k % 3;
            gr[k] = Gb + (size_t)(refl(il + di - 1) * 64 + refl(jl + dj - 1)) * HWH;
        }

        float v[16];
        float mx = -3.4e38f;
        #pragma unroll
        for (int i = 0; i < 16; i++) {
            int m = tid + i * 256;
            int im = m >> 6, jm = m & 63;
            float acc = 0.f;
            #pragma unroll
            for (int di = 0; di < 3; di++) {
                int ci = refl(im + di - 1) * 64;
                #pragma unroll
                for (int dj = 0; dj < 3; dj++)
                    acc += s2[di * 3 + dj] * gr[di * 3 + dj][ci + refl(jm + dj - 1)];
            }
            v[i] = acc;
            mx = fmaxf(mx, acc);
        }
        __syncthreads();   // guard red[] reuse across row-passes
        red[tid] = mx; __syncthreads();
        for (int st = 128; st > 0; st >>= 1) {
            if (tid < st) red[tid] = fmaxf(red[tid], red[tid + st]);
            __syncthreads();
        }
        mx = red[0];
        __syncthreads();

        float sum = 0.f;
        #pragma unroll
        for (int i = 0; i < 16; i++) {
            v[i] = __expf(v[i] - mx);
            sum += v[i];
        }
        red[tid] = sum; __syncthreads();
        for (int st = 128; st > 0; st >>= 1) {
            if (tid < st) red[tid] += red[tid + st];
            __syncthreads();
        }
        float inv = 1.f / red[0];

        f16* pr = d_P + ((size_t)b * HWH + l) * HWH;
        #pragma unroll
        for (int i = 0; i < 16; i++)
            pr[tid + i * 256] = __float2half_rn(v[i] * inv);
    }
}

// ---------------- host ----------------
#define SYM(p, s) do { void* _t; cudaGetSymbolAddress(&_t, s); p = (decltype(p))_t; } while (0)

#define LAUNCH_GEMM(ASPL, BSPL, OUTM, BIASM, WM, WN, BM, BN, NST, Ah, Al, Bh, Bl, bias, C0, C1, M, N, K, sa, sb, sc) \
    do { \
        auto kfn = gemm_pl<ASPL, BSPL, OUTM, BIASM, WM, WN, BM, BN, NST>; \
        int smemB = (NST) * ((1 + ASPL) * (BM) + (1 + BSPL) * (BN)) * SPAD * 2; \
        cudaFuncSetAttribute(kfn, cudaFuncAttributeMaxDynamicSharedMemorySize, smemB); \
        kfn<<<dim3((N) / (BN), (M) / (BM), BB), 256, smemB>>>( \
            Ah, Al, Bh, Bl, bias, C0, C1, M, N, K, sa, sb, sc); \
    } while (0)

extern "C" void kernel_launch(void* const* d_in, const int* in_sizes, int n_in,
                              void* d_out, int out_size) {
    (void)in_sizes; (void)n_in; (void)out_size;
    const float* content = (const float*)d_in[0];
    const float* style   = (const float*)d_in[1];
    const float* fusion  = (const float*)d_in[2];
    const float* theta_b = (const float*)d_in[4];
    const float* phi_b   = (const float*)d_in[6];
    const float* g_b     = (const float*)d_in[8];
    const float* W_b     = (const float*)d_in[10];
    const float* scale   = (const float*)d_in[11];
    float* out = (float*)d_out;

    f16 *xnT_hi, *xnT_lo, *snT_hi, *snT_lo, *fsT_hi, *fsT_lo;
    f16 *thw_hi, *thw_lo, *phw_hi, *phw_lo, *gw_hi, *gw_lo, *Ww_hi, *Ww_lo;
    f16 *thT_hi, *thT_lo, *phT_hi, *phT_lo;
    f16 *gT_hi, *gT_lo, *Pp;
    f16 *y_hi, *y_lo;
    float* Gp;
    SYM(xnT_hi, d_xnT_hi); SYM(xnT_lo, d_xnT_lo);
    SYM(snT_hi, d_snT_hi); SYM(snT_lo, d_snT_lo);
    SYM(fsT_hi, d_fsT_hi); SYM(fsT_lo, d_fsT_lo);
    SYM(thw_hi, d_thw_hi); SYM(thw_lo, d_thw_lo);
    SYM(phw_hi, d_phw_hi); SYM(phw_lo, d_phw_lo);
    SYM(gw_hi,  d_gw_hi);  SYM(gw_lo,  d_gw_lo);
    SYM(Ww_hi,  d_Ww_hi);  SYM(Ww_lo,  d_Ww_lo);
    SYM(thT_hi, d_thT_hi); SYM(thT_lo, d_thT_lo);
    SYM(phT_hi, d_phT_hi); SYM(phT_lo, d_phT_lo);
    SYM(gT_hi,  d_gT_hi);  SYM(gT_lo,  d_gT_lo);
    SYM(Pp,     d_P);
    SYM(y_hi,   d_y_hi);   SYM(y_lo,   d_y_lo);
    SYM(Gp,     d_G);

    // 1) instance-norm stats
    stats_kernel<<<2 * BB * CC, 256>>>(content, style);
    // 2) normalize + transpose + split (fp16)
    norm_split_T<<<dim3(HWH / 32, CC / 32, 3 * BB), dim3(32, 8)>>>(content, style, fusion);
    // 3) weight splits (fp16)
    weight_split<<<(ICI * CC) / 256, 256>>>((const float*)d_in[3], (const float*)d_in[5],
                                            (const float*)d_in[7], (const float*)d_in[9]);

    // 4) theta_xT : M=4096, N=256, K=512, 3-pass fp16-split
    LAUNCH_GEMM(1, 1, 2, 2, 4, 2, 128, 64, 3,
                xnT_hi, xnT_lo, thw_hi, thw_lo, theta_b, thT_hi, thT_lo,
                HWH, ICI, CC, (long long)HWH * CC, 0LL, (long long)HWH * ICI);

    // 5) phi_sT
    LAUNCH_GEMM(1, 1, 2, 2, 4, 2, 128, 64, 3,
                snT_hi, snT_lo, phw_hi, phw_lo, phi_b, phT_hi, phT_lo,
                HWH, ICI, CC, (long long)HWH * CC, 0LL, (long long)HWH * ICI);

    // 6) g_sT : M=256, N=4096, K=512 -> split fp16
    LAUNCH_GEMM(1, 1, 2, 1, 4, 2, 128, 64, 3,
                gw_hi, gw_lo, fsT_hi, fsT_lo, g_b, gT_hi, gT_lo,
                ICI, HWH, CC, 0LL, (long long)HWH * CC, (long long)ICI * HWH);

    // 7) G = theta @ phi^T : M=N=4096, K=256 -> fp32, 3-pass
    LAUNCH_GEMM(1, 1, 0, 0, 2, 4, 128, 128, 2,
                thT_hi, thT_lo, phT_hi, phT_lo, (const float*)nullptr, Gp, (void*)nullptr,
                HWH, HWH, ICI, (long long)HWH * ICI, (long long)HWH * ICI, (long long)HWH * HWH);

    // 8) gather + softmax -> P (fp16), 2x2 patch per block
    attn_softmax_kernel<<<dim3(1024, BB), 256>>>(scale);

    // 9) y = P @ g_s : single pass (P fp16 x g_hi fp16), grid 256
    LAUNCH_GEMM(0, 0, 2, 0, 4, 2, 128, 64, 3,
                Pp, Pp, gT_hi, gT_hi, (const float*)nullptr, y_hi, y_lo,
                HWH, ICI, HWH, (long long)HWH * HWH, (long long)ICI * HWH, (long long)HWH * ICI);

    // 10) out = W_w @ y^T + W_b : M=512, N=4096, K=256 -> fp32, 3-pass
    LAUNCH_GEMM(1, 1, 0, 1, 2, 4, 128, 128, 2,
                Ww_hi, Ww_lo, y_hi, y_lo, W_b, out, (void*)nullptr,
                CC, HWH, ICI, 0LL, (long long)HWH * ICI, (long long)CC * HWH);
}

// round 15
// speedup vs baseline: 1.3267x; 1.0716x over previous
#include <cuda_runtime.h>
#include <cuda_bf16.h>
#include <cuda_fp16.h>
#include <math.h>
#include <stdint.h>

typedef __half f16;

#define BB   2
#define CC   512
#define HWH  4096
#define ICI  256
#define SPAD 40

// ---------------- scratch (all operands fp16 split) ----------------
__device__ float d_mean[2 * BB * CC];
__device__ float d_istd[2 * BB * CC];

__device__ f16 d_xnT_hi[(size_t)BB * HWH * CC];
__device__ f16 d_xnT_lo[(size_t)BB * HWH * CC];
__device__ f16 d_snT_hi[(size_t)BB * HWH * CC];
__device__ f16 d_snT_lo[(size_t)BB * HWH * CC];
__device__ f16 d_fsT_hi[(size_t)BB * HWH * CC];
__device__ f16 d_fsT_lo[(size_t)BB * HWH * CC];

__device__ f16 d_thw_hi[ICI * CC], d_thw_lo[ICI * CC];
__device__ f16 d_phw_hi[ICI * CC], d_phw_lo[ICI * CC];
__device__ f16 d_gw_hi [ICI * CC], d_gw_lo [ICI * CC];
__device__ f16 d_Ww_hi [CC * ICI], d_Ww_lo [CC * ICI];

__device__ f16 d_thT_hi[(size_t)BB * HWH * ICI];
__device__ f16 d_thT_lo[(size_t)BB * HWH * ICI];
__device__ f16 d_phT_hi[(size_t)BB * HWH * ICI];
__device__ f16 d_phT_lo[(size_t)BB * HWH * ICI];

__device__ f16 d_gT_hi[(size_t)BB * ICI * HWH];
__device__ f16 d_gT_lo[(size_t)BB * ICI * HWH];

__device__ float d_G[(size_t)BB * HWH * HWH];

__device__ f16 d_P[(size_t)BB * HWH * HWH];

__device__ f16 d_y_hi[(size_t)BB * HWH * ICI];
__device__ f16 d_y_lo[(size_t)BB * HWH * ICI];

// ------------- stats -------------
__global__ void stats_kernel(const float* __restrict__ content,
                             const float* __restrict__ style) {
    int idx = blockIdx.x;
    int which = idx >> 10;
    int bc = idx & 1023;
    const float* src = (which == 0 ? content : style) + (size_t)bc * HWH;
    double s = 0.0, s2 = 0.0;
    for (int i = threadIdx.x; i < HWH; i += 256) {
        float v = src[i];
        s += v; s2 += (double)v * v;
    }
    __shared__ double sh1[256], sh2[256];
    sh1[threadIdx.x] = s; sh2[threadIdx.x] = s2;
    __syncthreads();
    for (int st = 128; st > 0; st >>= 1) {
        if (threadIdx.x < st) {
            sh1[threadIdx.x] += sh1[threadIdx.x + st];
            sh2[threadIdx.x] += sh2[threadIdx.x + st];
        }
        __syncthreads();
    }
    if (threadIdx.x == 0) {
        double mean = sh1[0] / (double)HWH;
        double var = (sh2[0] - (double)HWH * mean * mean) / (double)(HWH - 1);
        d_mean[idx] = (float)mean;
        d_istd[idx] = (float)(1.0 / sqrt(var + 1e-5));
    }
}

// ------ normalize + transpose + split (fp16) ------
__global__ void norm_split_T(const float* __restrict__ content,
                             const float* __restrict__ style,
                             const float* __restrict__ fusion) {
    int zz = blockIdx.z;
    int src = zz >> 1, b = zz & 1;
    const float* in;
    f16 *oh, *ol;
    if (src == 0)      { in = content; oh = d_xnT_hi; ol = d_xnT_lo; }
    else if (src == 1) { in = style;   oh = d_snT_hi; ol = d_snT_lo; }
    else               { in = fusion;  oh = d_fsT_hi; ol = d_fsT_lo; }
    in += (size_t)b * CC * HWH;
    oh += (size_t)b * HWH * CC;
    ol += (size_t)b * HWH * CC;

    int p0 = blockIdx.x * 32, c0 = blockIdx.y * 32;
    __shared__ float tile[32][33];
    int tx = threadIdx.x, ty = threadIdx.y;
    #pragma unroll
    for (int i = 0; i < 4; i++) {
        int c = c0 + ty + i * 8;
        float v = in[(size_t)c * HWH + p0 + tx];
        if (src < 2) {
            int mi = src * 1024 + b * 512 + c;
            v = (v - d_mean[mi]) * d_istd[mi];
        }
        tile[ty + i * 8][tx] = v;
    }
    __syncthreads();
    #pragma unroll
    for (int i = 0; i < 4; i++) {
        int p = p0 + ty + i * 8;
        int c = c0 + tx;
        float v = tile[tx][ty + i * 8];
        f16 h = __float2half_rn(v);
        size_t off = (size_t)p * CC + c;
        oh[off] = h;
        ol[off] = __float2half_rn(v - __half2float(h));
    }
}

// ------------- weight split (fp16) -------------
__global__ void weight_split(const float* __restrict__ tw, const float* __restrict__ pw,
                             const float* __restrict__ gw, const float* __restrict__ Ww) {
    int i = blockIdx.x * 256 + threadIdx.x;
    if (i >= ICI * CC) return;
    float v; f16 h;
    v = tw[i]; h = __float2half_rn(v); d_thw_hi[i] = h; d_thw_lo[i] = __float2half_rn(v - __half2float(h));
    v = pw[i]; h = __float2half_rn(v); d_phw_hi[i] = h; d_phw_lo[i] = __float2half_rn(v - __half2float(h));
    v = gw[i]; h = __float2half_rn(v); d_gw_hi[i]  = h; d_gw_lo[i]  = __float2half_rn(v - __half2float(h));
    v = Ww[i]; h = __float2half_rn(v); d_Ww_hi[i]  = h; d_Ww_lo[i]  = __float2half_rn(v - __half2float(h));
}

// ---------------- low-level helpers ----------------
__device__ __forceinline__ uint32_t smem_u32(const void* p) {
    uint32_t a;
    asm("{ .reg .u64 t; cvta.to.shared.u64 t, %1; cvt.u32.u64 %0, t; }"
        : "=r"(a) : "l"(p));
    return a;
}

__device__ __forceinline__ void cp16(uint32_t dst, const void* src) {
    asm volatile("cp.async.cg.shared.global [%0], [%1], 16;\n" :: "r"(dst), "l"(src));
}
__device__ __forceinline__ void cp_commit() { asm volatile("cp.async.commit_group;\n"); }
template<int N> __device__ __forceinline__ void cp_wait() {
    asm volatile("cp.async.wait_group %0;\n" :: "n"(N));
}

__device__ __forceinline__ void ldsm4(unsigned r[4], uint32_t addr) {
    asm volatile("ldmatrix.sync.aligned.m8n8.x4.shared.b16 {%0,%1,%2,%3}, [%4];"
                 : "=r"(r[0]), "=r"(r[1]), "=r"(r[2]), "=r"(r[3]) : "r"(addr));
}

__device__ __forceinline__ void mmaf16(float c[4], const unsigned a[4], const unsigned b[2]) {
    asm volatile(
        "mma.sync.aligned.m16n8k16.row.col.f32.f16.f16.f32 "
        "{%0,%1,%2,%3},{%4,%5,%6,%7},{%8,%9},{%0,%1,%2,%3};\n"
        : "+f"(c[0]), "+f"(c[1]), "+f"(c[2]), "+f"(c[3])
        : "r"(a[0]), "r"(a[1]), "r"(a[2]), "r"(a[3]), "r"(b[0]), "r"(b[1]));
}

// ---------------- pipelined NT GEMM (fp16): NST stages, fissioned MMA passes ----------------
template<int ASPL, int BSPL, int OUTM, int BIASM, int WM_, int WN_, int BM, int BN, int NST>
__global__ __launch_bounds__(256)
void gemm_pl(const void* __restrict__ Ahi_, const void* __restrict__ Alo_,
             const void* __restrict__ Bhi_, const void* __restrict__ Blo_,
             const float* __restrict__ bias,
             void* __restrict__ C0, void* __restrict__ C1,
             int M, int N, int K,
             long long sA, long long sB, long long sC) {
    constexpr int NPA = 1 + ASPL, NPB = 1 + BSPL;
    constexpr int FM = BM / (16 * WM_), FN = BN / (8 * WN_);
    constexpr int ABYT = BM * SPAD * 2;
    constexpr int BBYT = BN * SPAD * 2;
    constexpr int SSB = NPA * ABYT + NPB * BBYT;
    extern __shared__ char sh[];
    const uint32_t sbase = smem_u32(sh);

    const int bz = blockIdx.z;
    const unsigned short* Ah = (const unsigned short*)Ahi_ + (size_t)bz * sA;
    const unsigned short* Al = (const unsigned short*)Alo_ + (size_t)bz * sA;
    const unsigned short* Bh = (const unsigned short*)Bhi_ + (size_t)bz * sB;
    const unsigned short* Bl = (const unsigned short*)Blo_ + (size_t)bz * sB;

    const int m0 = blockIdx.y * BM, n0 = blockIdx.x * BN;
    const int tid = threadIdx.x, warp = tid >> 5, lane = tid & 31;
    const int wm = warp / WN_, wn = warp % WN_;
    const int grp = lane >> 2, qid = lane & 3;

    const int r8 = lane & 7, mi = lane >> 3;
    const uint32_t aLane = (uint32_t)(((r8 + ((mi & 1) << 3)) * SPAD + ((mi >> 1) << 3)) * 2);
    const uint32_t bLane = (uint32_t)(((r8 + ((mi >> 1) << 3)) * SPAD + ((mi & 1) << 3)) * 2);

    float acc[FM][FN][4] = {};

    auto load_stage = [&](int st, int kt) {
        #pragma unroll
        for (int v = 0; v < NPA; v++) {
            const unsigned short* g = v ? Al : Ah;
            uint32_t base = sbase + st * SSB + v * ABYT;
            #pragma unroll
            for (int cid = tid; cid < BM * 4; cid += 256) {
                int row = cid >> 2, seg = cid & 3;
                cp16(base + (uint32_t)((row * SPAD + seg * 8) * 2),
                     g + (size_t)(m0 + row) * K + kt + seg * 8);
            }
        }
        #pragma unroll
        for (int v = 0; v < NPB; v++) {
            const unsigned short* g = v ? Bl : Bh;
            uint32_t base = sbase + st * SSB + NPA * ABYT + v * BBYT;
            #pragma unroll
            for (int cid = tid; cid < BN * 4; cid += 256) {
                int row = cid >> 2, seg = cid & 3;
                cp16(base + (uint32_t)((row * SPAD + seg * 8) * 2),
                     g + (size_t)(n0 + row) * K + kt + seg * 8);
            }
        }
    };

    const int KT = K / 32;
    #pragma unroll
    for (int p = 0; p < NST - 1; p++) {
        if (p < KT) { load_stage(p, p * 32); cp_commit(); }
    }

    for (int it = 0; it < KT; ++it) {
        const int st = it % NST;
        if (KT - 1 - it >= NST - 2) cp_wait<(NST >= 2 ? NST - 2 : 0)>();
        else                        cp_wait<0>();
        __syncthreads();

        const int nx = it + NST - 1;
        if (nx < KT) { load_stage(nx % NST, nx * 32); cp_commit(); }

        const uint32_t sA0 = sbase + st * SSB;
        const uint32_t sA1 = sA0 + ABYT;
        const uint32_t sB0 = sbase + st * SSB + NPA * ABYT;
        const uint32_t sB1 = sB0 + BBYT;

        #pragma unroll
        for (int kk = 0; kk < 2; kk++) {
            const uint32_t koff = kk * 32;
            unsigned a[FM][4], a2[FM][4], b0[FN][2], b1[FN][2];
            #pragma unroll
            for (int nn2 = 0; nn2 < FN / 2; nn2++) {
                uint32_t boff = bLane + (uint32_t)((wn * FN * 8 + nn2 * 16) * SPAD * 2) + koff;
                ldsm4(&b0[2 * nn2][0], sB0 + boff);
                if (BSPL) ldsm4(&b1[2 * nn2][0], sB1 + boff);
            }
            #pragma unroll
            for (int mm = 0; mm < FM; mm++) {
                uint32_t aoff = aLane + (uint32_t)((wm * FM * 16 + mm * 16) * SPAD * 2) + koff;
                ldsm4(a[mm], sA0 + aoff);
                if (ASPL) ldsm4(a2[mm], sA1 + aoff);
            }
            // pass 1: hi*hi — independent accumulator chains
            #pragma unroll
            for (int mm = 0; mm < FM; mm++)
                #pragma unroll
                for (int nn = 0; nn < FN; nn++)
                    mmaf16(acc[mm][nn], a[mm], b0[nn]);
            // pass 2: hi*lo
            if (BSPL) {
                #pragma unroll
                for (int mm = 0; mm < FM; mm++)
                    #pragma unroll
                    for (int nn = 0; nn < FN; nn++)
                        mmaf16(acc[mm][nn], a[mm], b1[nn]);
            }
            // pass 3: lo*hi
            if (ASPL) {
                #pragma unroll
                for (int mm = 0; mm < FM; mm++)
                    #pragma unroll
                    for (int nn = 0; nn < FN; nn++)
                        mmaf16(acc[mm][nn], a2[mm], b0[nn]);
            }
        }
    }

    #pragma unroll
    for (int mm = 0; mm < FM; mm++) {
        #pragma unroll
        for (int nn = 0; nn < FN; nn++) {
            #pragma unroll
            for (int half = 0; half < 2; half++) {
                int row = m0 + wm * (FM * 16) + mm * 16 + grp + half * 8;
                int col = n0 + wn * (FN * 8) + nn * 8 + qid * 2;
                float v0 = acc[mm][nn][half * 2 + 0];
                float v1 = acc[mm][nn][half * 2 + 1];
                if (BIASM == 1) { float bb = bias[row]; v0 += bb; v1 += bb; }
                if (BIASM == 2) { v0 += bias[col]; v1 += bias[col + 1]; }
                size_t off = (size_t)bz * sC + (size_t)row * N + col;
                if (OUTM == 0) {
                    float2 p; p.x = v0; p.y = v1;
                    *(float2*)((float*)C0 + off) = p;
                } else {
                    f16 h0 = __float2half_rn(v0), h1 = __float2half_rn(v1);
                    f16 l0 = __float2half_rn(v0 - __half2float(h0));
                    f16 l1 = __float2half_rn(v1 - __half2float(h1));
                    __half2 hp; hp.x = h0; hp.y = h1;
                    __half2 lp; lp.x = l0; lp.y = l1;
                    *(__half2*)((f16*)C0 + off) = hp;
                    *(__half2*)((f16*)C1 + off) = lp;
                }
            }
        }
    }
}

// ------- fused f-assembly + softmax, 2x2 l-patch per block (NOT unrolled), P -> fp16 -------
__device__ __forceinline__ int refl(int i) {
    return i < 0 ? -i : (i > 63 ? 126 - i : i);
}

__global__ __launch_bounds__(256)
void attn_softmax_kernel(const float* __restrict__ scale) {
    const int bx = blockIdx.x;          // 0..1023 : 32x32 patch grid
    const int b = blockIdx.y;
    const int pil = bx >> 5, pjl = bx & 31;
    const int tid = threadIdx.x;

    __shared__ float red[256];

    const float* Gb = d_G + (size_t)b * HWH * HWH;
    float s2[9];
    #pragma unroll
    for (int k = 0; k < 9; k++) {
        float s = scale[k];
        s2[k] = s * s;
    }

    // IMPORTANT: not unrolled — keeps one v[16] generation live (no spills)
    #pragma unroll 1
    for (int rr = 0; rr < 4; rr++) {
        const int il = 2 * pil + (rr >> 1);
        const int jl = 2 * pjl + (rr & 1);
        const int l = il * 64 + jl;

        const float* gr[9];
        #pragma unroll
        for (int k = 0; k < 9; k++) {
            int di = k / 3, dj = k % 3;
            gr[k] = Gb + (size_t)(refl(il + di - 1) * 64 + refl(jl + dj - 1)) * HWH;
        }

        float v[16];
        float mx = -3.4e38f;
        #pragma unroll
        for (int i = 0; i < 16; i++) {
            int m = tid + i * 256;
            int im = m >> 6, jm = m & 63;
            float acc = 0.f;
            #pragma unroll
            for (int di = 0; di < 3; di++) {
                int ci = refl(im + di - 1) * 64;
                #pragma unroll
                for (int dj = 0; dj < 3; dj++)
                    acc += s2[di * 3 + dj] * gr[di * 3 + dj][ci + refl(jm + dj - 1)];
            }
            v[i] = acc;
            mx = fmaxf(mx, acc);
        }
        __syncthreads();   // guard red[] reuse across row-passes
        red[tid] = mx; __syncthreads();
        for (int st = 128; st > 0; st >>= 1) {
            if (tid < st) red[tid] = fmaxf(red[tid], red[tid + st]);
            __syncthreads();
        }
        mx = red[0];
        __syncthreads();

        float sum = 0.f;
        #pragma unroll
        for (int i = 0; i < 16; i++) {
            v[i] = __expf(v[i] - mx);
            sum += v[i];
        }
        red[tid] = sum; __syncthreads();
        for (int st = 128; st > 0; st >>= 1) {
            if (tid < st) red[tid] += red[tid + st];
            __syncthreads();
        }
        float inv = 1.f / red[0];

        f16* pr = d_P + ((size_t)b * HWH + l) * HWH;
        #pragma unroll
        for (int i = 0; i < 16; i++)
            pr[tid + i * 256] = __float2half_rn(v[i] * inv);
    }
}

// ---------------- host ----------------
#define SYM(p, s) do { void* _t; cudaGetSymbolAddress(&_t, s); p = (decltype(p))_t; } while (0)

#define LAUNCH_GEMM(ASPL, BSPL, OUTM, BIASM, WM, WN, BM, BN, NST, Ah, Al, Bh, Bl, bias, C0, C1, M, N, K, sa, sb, sc) \
    do { \
        auto kfn = gemm_pl<ASPL, BSPL, OUTM, BIASM, WM, WN, BM, BN, NST>; \
        int smemB = (NST) * ((1 + ASPL) * (BM) + (1 + BSPL) * (BN)) * SPAD * 2; \
        cudaFuncSetAttribute(kfn, cudaFuncAttributeMaxDynamicSharedMemorySize, smemB); \
        kfn<<<dim3((N) / (BN), (M) / (BM), BB), 256, smemB>>>( \
            Ah, Al, Bh, Bl, bias, C0, C1, M, N, K, sa, sb, sc); \
    } while (0)

extern "C" void kernel_launch(void* const* d_in, const int* in_sizes, int n_in,
                              void* d_out, int out_size) {
    (void)in_sizes; (void)n_in; (void)out_size;
    const float* content = (const float*)d_in[0];
    const float* style   = (const float*)d_in[1];
    const float* fusion  = (const float*)d_in[2];
    const float* theta_b = (const float*)d_in[4];
    const float* phi_b   = (const float*)d_in[6];
    const float* g_b     = (const float*)d_in[8];
    const float* W_b     = (const float*)d_in[10];
    const float* scale   = (const float*)d_in[11];
    float* out = (float*)d_out;

    f16 *xnT_hi, *xnT_lo, *snT_hi, *snT_lo, *fsT_hi, *fsT_lo;
    f16 *thw_hi, *thw_lo, *phw_hi, *phw_lo, *gw_hi, *gw_lo, *Ww_hi, *Ww_lo;
    f16 *thT_hi, *thT_lo, *phT_hi, *phT_lo;
    f16 *gT_hi, *gT_lo, *Pp;
    f16 *y_hi, *y_lo;
    float* Gp;
    SYM(xnT_hi, d_xnT_hi); SYM(xnT_lo, d_xnT_lo);
    SYM(snT_hi, d_snT_hi); SYM(snT_lo, d_snT_lo);
    SYM(fsT_hi, d_fsT_hi); SYM(fsT_lo, d_fsT_lo);
    SYM(thw_hi, d_thw_hi); SYM(thw_lo, d_thw_lo);
    SYM(phw_hi, d_phw_hi); SYM(phw_lo, d_phw_lo);
    SYM(gw_hi,  d_gw_hi);  SYM(gw_lo,  d_gw_lo);
    SYM(Ww_hi,  d_Ww_hi);  SYM(Ww_lo,  d_Ww_lo);
    SYM(thT_hi, d_thT_hi); SYM(thT_lo, d_thT_lo);
    SYM(phT_hi, d_phT_hi); SYM(phT_lo, d_phT_lo);
    SYM(gT_hi,  d_gT_hi);  SYM(gT_lo,  d_gT_lo);
    SYM(Pp,     d_P);
    SYM(y_hi,   d_y_hi);   SYM(y_lo,   d_y_lo);
    SYM(Gp,     d_G);

    // 1) instance-norm stats
    stats_kernel<<<2 * BB * CC, 256>>>(content, style);
    // 2) normalize + transpose + split (fp16)
    norm_split_T<<<dim3(HWH / 32, CC / 32, 3 * BB), dim3(32, 8)>>>(content, style, fusion);
    // 3) weight splits (fp16)
    weight_split<<<(ICI * CC) / 256, 256>>>((const float*)d_in[3], (const float*)d_in[5],
                                            (const float*)d_in[7], (const float*)d_in[9]);

    // 4) theta_xT : M=4096, N=256, K=512, 3-pass fp16-split
    LAUNCH_GEMM(1, 1, 2, 2, 4, 2, 128, 64, 3,
                xnT_hi, xnT_lo, thw_hi, thw_lo, theta_b, thT_hi, thT_lo,
                HWH, ICI, CC, (long long)HWH * CC, 0LL, (long long)HWH * ICI);

    // 5) phi_sT
    LAUNCH_GEMM(1, 1, 2, 2, 4, 2, 128, 64, 3,
                snT_hi, snT_lo, phw_hi, phw_lo, phi_b, phT_hi, phT_lo,
                HWH, ICI, CC, (long long)HWH * CC, 0LL, (long long)HWH * ICI);

    // 6) g_sT : M=256, N=4096, K=512 -> split fp16
    LAUNCH_GEMM(1, 1, 2, 1, 4, 2, 128, 64, 3,
                gw_hi, gw_lo, fsT_hi, fsT_lo, g_b, gT_hi, gT_lo,
                ICI, HWH, CC, 0LL, (long long)HWH * CC, (long long)ICI * HWH);

    // 7) G = theta @ phi^T : M=N=4096, K=256 -> fp32, 3-pass
    LAUNCH_GEMM(1, 1, 0, 0, 2, 4, 128, 128, 2,
                thT_hi, thT_lo, phT_hi, phT_lo, (const float*)nullptr, Gp, (void*)nullptr,
                HWH, HWH, ICI, (long long)HWH * ICI, (long long)HWH * ICI, (long long)HWH * HWH);

    // 8) gather + softmax -> P (fp16), 2x2 patch per block, rr loop NOT unrolled
    attn_softmax_kernel<<<dim3(1024, BB), 256>>>(scale);

    // 9) y = P @ g_s : single pass (P fp16 x g_hi fp16), grid 256
    LAUNCH_GEMM(0, 0, 2, 0, 4, 2, 128, 64, 3,
                Pp, Pp, gT_hi, gT_hi, (const float*)nullptr, y_hi, y_lo,
                HWH, ICI, HWH, (long long)HWH * HWH, (long long)ICI * HWH, (long long)HWH * ICI);

    // 10) out = W_w @ y^T + W_b : M=512, N=4096, K=256 -> fp32, 3-pass
    LAUNCH_GEMM(1, 1, 0, 1, 2, 4, 128, 128, 2,
                Ww_hi, Ww_lo, y_hi, y_lo, W_b, out, (void*)nullptr,
                CC, HWH, ICI, 0LL, (long long)HWH * ICI, (long long)CC * HWH);
}

// round 16
// speedup vs baseline: 1.3563x; 1.0223x over previous
#include <cuda_runtime.h>
#include <cuda_bf16.h>
#include <cuda_fp16.h>
#include <math.h>
#include <stdint.h>

typedef __half f16;

#define BB   2
#define CC   512
#define HWH  4096
#define ICI  256
#define SPAD 40
#define CAND_CAP 64

// ---------------- scratch (all operands fp16 split) ----------------
__device__ float d_mean[2 * BB * CC];
__device__ float d_istd[2 * BB * CC];

__device__ f16 d_xnT_hi[(size_t)BB * HWH * CC];
__device__ f16 d_xnT_lo[(size_t)BB * HWH * CC];
__device__ f16 d_snT_hi[(size_t)BB * HWH * CC];
__device__ f16 d_snT_lo[(size_t)BB * HWH * CC];
__device__ f16 d_fsT_hi[(size_t)BB * HWH * CC];
__device__ f16 d_fsT_lo[(size_t)BB * HWH * CC];

__device__ f16 d_thw_hi[ICI * CC], d_thw_lo[ICI * CC];
__device__ f16 d_phw_hi[ICI * CC], d_phw_lo[ICI * CC];
__device__ f16 d_gw_hi [ICI * CC], d_gw_lo [ICI * CC];
__device__ f16 d_Ww_hi [CC * ICI], d_Ww_lo [CC * ICI];

__device__ f16 d_thT_hi[(size_t)BB * HWH * ICI];
__device__ f16 d_thT_lo[(size_t)BB * HWH * ICI];
__device__ f16 d_phT_hi[(size_t)BB * HWH * ICI];
__device__ f16 d_phT_lo[(size_t)BB * HWH * ICI];

__device__ f16 d_gT_hi[(size_t)BB * ICI * HWH];

__device__ f16 d_G[(size_t)BB * HWH * HWH];   // fp16 screening G

__device__ f16 d_P[(size_t)BB * HWH * HWH];

__device__ f16 d_y_hi[(size_t)BB * HWH * ICI];
__device__ f16 d_y_lo[(size_t)BB * HWH * ICI];

// ------------- stats -------------
__global__ void stats_kernel(const float* __restrict__ content,
                             const float* __restrict__ style) {
    int idx = blockIdx.x;
    int which = idx >> 10;
    int bc = idx & 1023;
    const float* src = (which == 0 ? content : style) + (size_t)bc * HWH;
    double s = 0.0, s2 = 0.0;
    for (int i = threadIdx.x; i < HWH; i += 256) {
        float v = src[i];
        s += v; s2 += (double)v * v;
    }
    __shared__ double sh1[256], sh2[256];
    sh1[threadIdx.x] = s; sh2[threadIdx.x] = s2;
    __syncthreads();
    for (int st = 128; st > 0; st >>= 1) {
        if (threadIdx.x < st) {
            sh1[threadIdx.x] += sh1[threadIdx.x + st];
            sh2[threadIdx.x] += sh2[threadIdx.x + st];
        }
        __syncthreads();
    }
    if (threadIdx.x == 0) {
        double mean = sh1[0] / (double)HWH;
        double var = (sh2[0] - (double)HWH * mean * mean) / (double)(HWH - 1);
        d_mean[idx] = (float)mean;
        d_istd[idx] = (float)(1.0 / sqrt(var + 1e-5));
    }
}

// ------ normalize + transpose + split (fp16) ------
__global__ void norm_split_T(const float* __restrict__ content,
                             const float* __restrict__ style,
                             const float* __restrict__ fusion) {
    int zz = blockIdx.z;
    int src = zz >> 1, b = zz & 1;
    const float* in;
    f16 *oh, *ol;
    if (src == 0)      { in = content; oh = d_xnT_hi; ol = d_xnT_lo; }
    else if (src == 1) { in = style;   oh = d_snT_hi; ol = d_snT_lo; }
    else               { in = fusion;  oh = d_fsT_hi; ol = d_fsT_lo; }
    in += (size_t)b * CC * HWH;
    oh += (size_t)b * HWH * CC;
    ol += (size_t)b * HWH * CC;

    int p0 = blockIdx.x * 32, c0 = blockIdx.y * 32;
    __shared__ float tile[32][33];
    int tx = threadIdx.x, ty = threadIdx.y;
    #pragma unroll
    for (int i = 0; i < 4; i++) {
        int c = c0 + ty + i * 8;
        float v = in[(size_t)c * HWH + p0 + tx];
        if (src < 2) {
            int mi = src * 1024 + b * 512 + c;
            v = (v - d_mean[mi]) * d_istd[mi];
        }
        tile[ty + i * 8][tx] = v;
    }
    __syncthreads();
    #pragma unroll
    for (int i = 0; i < 4; i++) {
        int p = p0 + ty + i * 8;
        int c = c0 + tx;
        float v = tile[tx][ty + i * 8];
        f16 h = __float2half_rn(v);
        size_t off = (size_t)p * CC + c;
        oh[off] = h;
        ol[off] = __float2half_rn(v - __half2float(h));
    }
}

// ------------- weight split (fp16) -------------
__global__ void weight_split(const float* __restrict__ tw, const float* __restrict__ pw,
                             const float* __restrict__ gw, const float* __restrict__ Ww) {
    int i = blockIdx.x * 256 + threadIdx.x;
    if (i >= ICI * CC) return;
    float v; f16 h;
    v = tw[i]; h = __float2half_rn(v); d_thw_hi[i] = h; d_thw_lo[i] = __float2half_rn(v - __half2float(h));
    v = pw[i]; h = __float2half_rn(v); d_phw_hi[i] = h; d_phw_lo[i] = __float2half_rn(v - __half2float(h));
    v = gw[i]; h = __float2half_rn(v); d_gw_hi[i]  = h; d_gw_lo[i]  = __float2half_rn(v - __half2float(h));
    v = Ww[i]; h = __float2half_rn(v); d_Ww_hi[i]  = h; d_Ww_lo[i]  = __float2half_rn(v - __half2float(h));
}

// ---------------- low-level helpers ----------------
__device__ __forceinline__ uint32_t smem_u32(const void* p) {
    uint32_t a;
    asm("{ .reg .u64 t; cvta.to.shared.u64 t, %1; cvt.u32.u64 %0, t; }"
        : "=r"(a) : "l"(p));
    return a;
}

__device__ __forceinline__ void cp16(uint32_t dst, const void* src) {
    asm volatile("cp.async.cg.shared.global [%0], [%1], 16;\n" :: "r"(dst), "l"(src));
}
__device__ __forceinline__ void cp_commit() { asm volatile("cp.async.commit_group;\n"); }
template<int N> __device__ __forceinline__ void cp_wait() {
    asm volatile("cp.async.wait_group %0;\n" :: "n"(N));
}

__device__ __forceinline__ void ldsm4(unsigned r[4], uint32_t addr) {
    asm volatile("ldmatrix.sync.aligned.m8n8.x4.shared.b16 {%0,%1,%2,%3}, [%4];"
                 : "=r"(r[0]), "=r"(r[1]), "=r"(r[2]), "=r"(r[3]) : "r"(addr));
}

__device__ __forceinline__ void mmaf16(float c[4], const unsigned a[4], const unsigned b[2]) {
    asm volatile(
        "mma.sync.aligned.m16n8k16.row.col.f32.f16.f16.f32 "
        "{%0,%1,%2,%3},{%4,%5,%6,%7},{%8,%9},{%0,%1,%2,%3};\n"
        : "+f"(c[0]), "+f"(c[1]), "+f"(c[2]), "+f"(c[3])
        : "r"(a[0]), "r"(a[1]), "r"(a[2]), "r"(a[3]), "r"(b[0]), "r"(b[1]));
}

// ---------------- pipelined NT GEMM (fp16): NST stages, fissioned MMA passes ----------------
// OUTM: 0 fp32, 2 split fp16, 3 plain fp16. BIASM: 0 none, 1 bias[row], 2 bias[col].
template<int ASPL, int BSPL, int OUTM, int BIASM, int WM_, int WN_, int BM, int BN, int NST>
__global__ __launch_bounds__(256)
void gemm_pl(const void* __restrict__ Ahi_, const void* __restrict__ Alo_,
             const void* __restrict__ Bhi_, const void* __restrict__ Blo_,
             const float* __restrict__ bias,
             void* __restrict__ C0, void* __restrict__ C1,
             int M, int N, int K,
             long long sA, long long sB, long long sC) {
    constexpr int NPA = 1 + ASPL, NPB = 1 + BSPL;
    constexpr int FM = BM / (16 * WM_), FN = BN / (8 * WN_);
    constexpr int ABYT = BM * SPAD * 2;
    constexpr int BBYT = BN * SPAD * 2;
    constexpr int SSB = NPA * ABYT + NPB * BBYT;
    extern __shared__ char sh[];
    const uint32_t sbase = smem_u32(sh);

    const int bz = blockIdx.z;
    const unsigned short* Ah = (const unsigned short*)Ahi_ + (size_t)bz * sA;
    const unsigned short* Al = (const unsigned short*)Alo_ + (size_t)bz * sA;
    const unsigned short* Bh = (const unsigned short*)Bhi_ + (size_t)bz * sB;
    const unsigned short* Bl = (const unsigned short*)Blo_ + (size_t)bz * sB;

    const int m0 = blockIdx.y * BM, n0 = blockIdx.x * BN;
    const int tid = threadIdx.x, warp = tid >> 5, lane = tid & 31;
    const int wm = warp / WN_, wn = warp % WN_;
    const int grp = lane >> 2, qid = lane & 3;

    const int r8 = lane & 7, mi = lane >> 3;
    const uint32_t aLane = (uint32_t)(((r8 + ((mi & 1) << 3)) * SPAD + ((mi >> 1) << 3)) * 2);
    const uint32_t bLane = (uint32_t)(((r8 + ((mi >> 1) << 3)) * SPAD + ((mi & 1) << 3)) * 2);

    float acc[FM][FN][4] = {};

    auto load_stage = [&](int st, int kt) {
        #pragma unroll
        for (int v = 0; v < NPA; v++) {
            const unsigned short* g = v ? Al : Ah;
            uint32_t base = sbase + st * SSB + v * ABYT;
            #pragma unroll
            for (int cid = tid; cid < BM * 4; cid += 256) {
                int row = cid >> 2, seg = cid & 3;
                cp16(base + (uint32_t)((row * SPAD + seg * 8) * 2),
                     g + (size_t)(m0 + row) * K + kt + seg * 8);
            }
        }
        #pragma unroll
        for (int v = 0; v < NPB; v++) {
            const unsigned short* g = v ? Bl : Bh;
            uint32_t base = sbase + st * SSB + NPA * ABYT + v * BBYT;
            #pragma unroll
            for (int cid = tid; cid < BN * 4; cid += 256) {
                int row = cid >> 2, seg = cid & 3;
                cp16(base + (uint32_t)((row * SPAD + seg * 8) * 2),
                     g + (size_t)(n0 + row) * K + kt + seg * 8);
            }
        }
    };

    const int KT = K / 32;
    #pragma unroll
    for (int p = 0; p < NST - 1; p++) {
        if (p < KT) { load_stage(p, p * 32); cp_commit(); }
    }

    for (int it = 0; it < KT; ++it) {
        const int st = it % NST;
        if (KT - 1 - it >= NST - 2) cp_wait<(NST >= 2 ? NST - 2 : 0)>();
        else                        cp_wait<0>();
        __syncthreads();

        const int nx = it + NST - 1;
        if (nx < KT) { load_stage(nx % NST, nx * 32); cp_commit(); }

        const uint32_t sA0 = sbase + st * SSB;
        const uint32_t sA1 = sA0 + ABYT;
        const uint32_t sB0 = sbase + st * SSB + NPA * ABYT;
        const uint32_t sB1 = sB0 + BBYT;

        #pragma unroll
        for (int kk = 0; kk < 2; kk++) {
            const uint32_t koff = kk * 32;
            unsigned a[FM][4], a2[FM][4], b0[FN][2], b1[FN][2];
            #pragma unroll
            for (int nn2 = 0; nn2 < FN / 2; nn2++) {
                uint32_t boff = bLane + (uint32_t)((wn * FN * 8 + nn2 * 16) * SPAD * 2) + koff;
                ldsm4(&b0[2 * nn2][0], sB0 + boff);
                if (BSPL) ldsm4(&b1[2 * nn2][0], sB1 + boff);
            }
            #pragma unroll
            for (int mm = 0; mm < FM; mm++) {
                uint32_t aoff = aLane + (uint32_t)((wm * FM * 16 + mm * 16) * SPAD * 2) + koff;
                ldsm4(a[mm], sA0 + aoff);
                if (ASPL) ldsm4(a2[mm], sA1 + aoff);
            }
            #pragma unroll
            for (int mm = 0; mm < FM; mm++)
                #pragma unroll
                for (int nn = 0; nn < FN; nn++)
                    mmaf16(acc[mm][nn], a[mm], b0[nn]);
            if (BSPL) {
                #pragma unroll
                for (int mm = 0; mm < FM; mm++)
                    #pragma unroll
                    for (int nn = 0; nn < FN; nn++)
                        mmaf16(acc[mm][nn], a[mm], b1[nn]);
            }
            if (ASPL) {
                #pragma unroll
                for (int mm = 0; mm < FM; mm++)
                    #pragma unroll
                    for (int nn = 0; nn < FN; nn++)
                        mmaf16(acc[mm][nn], a2[mm], b0[nn]);
            }
        }
    }

    #pragma unroll
    for (int mm = 0; mm < FM; mm++) {
        #pragma unroll
        for (int nn = 0; nn < FN; nn++) {
            #pragma unroll
            for (int half = 0; half < 2; half++) {
                int row = m0 + wm * (FM * 16) + mm * 16 + grp + half * 8;
                int col = n0 + wn * (FN * 8) + nn * 8 + qid * 2;
                float v0 = acc[mm][nn][half * 2 + 0];
                float v1 = acc[mm][nn][half * 2 + 1];
                if (BIASM == 1) { float bb = bias[row]; v0 += bb; v1 += bb; }
                if (BIASM == 2) { v0 += bias[col]; v1 += bias[col + 1]; }
                size_t off = (size_t)bz * sC + (size_t)row * N + col;
                if (OUTM == 0) {
                    float2 p; p.x = v0; p.y = v1;
                    *(float2*)((float*)C0 + off) = p;
                } else if (OUTM == 2) {
                    f16 h0 = __float2half_rn(v0), h1 = __float2half_rn(v1);
                    f16 l0 = __float2half_rn(v0 - __half2float(h0));
                    f16 l1 = __float2half_rn(v1 - __half2float(h1));
                    __half2 hp; hp.x = h0; hp.y = h1;
                    __half2 lp; lp.x = l0; lp.y = l1;
                    *(__half2*)((f16*)C0 + off) = hp;
                    *(__half2*)((f16*)C1 + off) = lp;
                } else {   // OUTM == 3: plain fp16
                    __half2 hp;
                    hp.x = __float2half_rn(v0);
                    hp.y = __float2half_rn(v1);
                    *(__half2*)((f16*)C0 + off) = hp;
                }
            }
        }
    }
}

// ------- softmax with fp16 screening + exact candidate rescue -------
__device__ __forceinline__ int refl(int i) {
    return i < 0 ? -i : (i > 63 ? 126 - i : i);
}

__global__ __launch_bounds__(256)
void attn_softmax_kernel(const float* __restrict__ scale) {
    const int bx = blockIdx.x;          // 0..1023 : 32x32 patch grid
    const int b = blockIdx.y;
    const int pil = bx >> 5, pjl = bx & 31;
    const int tid = threadIdx.x;

    __shared__ float red[256];
    __shared__ int cand[CAND_CAP];
    __shared__ int ccount;

    const f16* Gb  = d_G + (size_t)b * HWH * HWH;
    const f16* thH = d_thT_hi + (size_t)b * HWH * ICI;
    const f16* thL = d_thT_lo + (size_t)b * HWH * ICI;
    const f16* phH = d_phT_hi + (size_t)b * HWH * ICI;
    const f16* phL = d_phT_lo + (size_t)b * HWH * ICI;

    float s2[9];
    #pragma unroll
    for (int k = 0; k < 9; k++) {
        float s = scale[k];
        s2[k] = s * s;
    }

    #pragma unroll 1
    for (int rr = 0; rr < 4; rr++) {
        const int il = 2 * pil + (rr >> 1);
        const int jl = 2 * pjl + (rr & 1);
        const int l = il * 64 + jl;

        int rl[9];
        const f16* gr[9];
        #pragma unroll
        for (int k = 0; k < 9; k++) {
            int di = k / 3, dj = k % 3;
            rl[k] = refl(il + di - 1) * 64 + refl(jl + dj - 1);
            gr[k] = Gb + (size_t)rl[k] * HWH;
        }

        // screening pass from fp16 G
        float v[16];
        float mx = -3.4e38f;
        #pragma unroll
        for (int i = 0; i < 16; i++) {
            int m = tid + i * 256;
            int im = m >> 6, jm = m & 63;
            float acc = 0.f;
            #pragma unroll
            for (int di = 0; di < 3; di++) {
                int ci = refl(im + di - 1) * 64;
                #pragma unroll
                for (int dj = 0; dj < 3; dj++)
                    acc += s2[di * 3 + dj] * __half2float(gr[di * 3 + dj][ci + refl(jm + dj - 1)]);
            }
            v[i] = acc;
            mx = fmaxf(mx, acc);
        }
        __syncthreads();
        red[tid] = mx; __syncthreads();
        for (int st = 128; st > 0; st >>= 1) {
            if (tid < st) red[tid] = fmaxf(red[tid], red[tid + st]);
            __syncthreads();
        }
        mx = red[0];
        __syncthreads();

        // collect candidates (logit > max - 15)
        if (tid == 0) ccount = 0;
        __syncthreads();
        const float thr = mx - 15.0f;
        #pragma unroll
        for (int i = 0; i < 16; i++) {
            if (v[i] > thr) {
                int s = atomicAdd(&ccount, 1);
                if (s < CAND_CAP) cand[s] = tid + i * 256;
            }
        }
        __syncthreads();
        int nc = ccount < CAND_CAP ? ccount : CAND_CAP;

        // preload theta patch rows at channel tid (exact limbs)
        float thv[9];
        #pragma unroll
        for (int k = 0; k < 9; k++)
            thv[k] = __half2float(thH[(size_t)rl[k] * ICI + tid])
                   + __half2float(thL[(size_t)rl[k] * ICI + tid]);

        // exact rescue of each candidate
        #pragma unroll 1
        for (int ci = 0; ci < nc; ci++) {
            int m = cand[ci];
            int im = m >> 6, jm = m & 63;
            float part = 0.f;
            #pragma unroll
            for (int k = 0; k < 9; k++) {
                int di = k / 3, dj = k % 3;
                int rm = refl(im + di - 1) * 64 + refl(jm + dj - 1);
                float ph = __half2float(phH[(size_t)rm * ICI + tid])
                         + __half2float(phL[(size_t)rm * ICI + tid]);
                part += s2[k] * thv[k] * ph;
            }
            red[tid] = part; __syncthreads();
            for (int st = 128; st > 0; st >>= 1) {
                if (tid < st) red[tid] += red[tid + st];
                __syncthreads();
            }
            float ex = red[0];
            if (tid == (m & 255)) v[m >> 8] = ex;
            __syncthreads();
        }

        // recompute max over corrected values
        float mx2 = -3.4e38f;
        #pragma unroll
        for (int i = 0; i < 16; i++) mx2 = fmaxf(mx2, v[i]);
        red[tid] = mx2; __syncthreads();
        for (int st = 128; st > 0; st >>= 1) {
            if (tid < st) red[tid] = fmaxf(red[tid], red[tid + st]);
            __syncthreads();
        }
        mx2 = red[0];
        __syncthreads();

        float sum = 0.f;
        #pragma unroll
        for (int i = 0; i < 16; i++) {
            v[i] = __expf(v[i] - mx2);
            sum += v[i];
        }
        red[tid] = sum; __syncthreads();
        for (int st = 128; st > 0; st >>= 1) {
            if (tid < st) red[tid] += red[tid + st];
            __syncthreads();
        }
        float inv = 1.f / red[0];

        f16* pr = d_P + ((size_t)b * HWH + l) * HWH;
        #pragma unroll
        for (int i = 0; i < 16; i++)
            pr[tid + i * 256] = __float2half_rn(v[i] * inv);
    }
}

// ---------------- host ----------------
#define SYM(p, s) do { void* _t; cudaGetSymbolAddress(&_t, s); p = (decltype(p))_t; } while (0)

#define LAUNCH_GEMM(ASPL, BSPL, OUTM, BIASM, WM, WN, BM, BN, NST, Ah, Al, Bh, Bl, bias, C0, C1, M, N, K, sa, sb, sc) \
    do { \
        auto kfn = gemm_pl<ASPL, BSPL, OUTM, BIASM, WM, WN, BM, BN, NST>; \
        int smemB = (NST) * ((1 + ASPL) * (BM) + (1 + BSPL) * (BN)) * SPAD * 2; \
        cudaFuncSetAttribute(kfn, cudaFuncAttributeMaxDynamicSharedMemorySize, smemB); \
        kfn<<<dim3((N) / (BN), (M) / (BM), BB), 256, smemB>>>( \
            Ah, Al, Bh, Bl, bias, C0, C1, M, N, K, sa, sb, sc); \
    } while (0)

extern "C" void kernel_launch(void* const* d_in, const int* in_sizes, int n_in,
                              void* d_out, int out_size) {
    (void)in_sizes; (void)n_in; (void)out_size;
    const float* content = (const float*)d_in[0];
    const float* style   = (const float*)d_in[1];
    const float* fusion  = (const float*)d_in[2];
    const float* theta_b = (const float*)d_in[4];
    const float* phi_b   = (const float*)d_in[6];
    const float* g_b     = (const float*)d_in[8];
    const float* W_b     = (const float*)d_in[10];
    const float* scale   = (const float*)d_in[11];
    float* out = (float*)d_out;

    f16 *xnT_hi, *xnT_lo, *snT_hi, *snT_lo, *fsT_hi, *fsT_lo;
    f16 *thw_hi, *thw_lo, *phw_hi, *phw_lo, *gw_hi, *gw_lo, *Ww_hi, *Ww_lo;
    f16 *thT_hi, *thT_lo, *phT_hi, *phT_lo;
    f16 *gT_hi, *Pp;
    f16 *y_hi, *y_lo;
    f16* Gp;
    SYM(xnT_hi, d_xnT_hi); SYM(xnT_lo, d_xnT_lo);
    SYM(snT_hi, d_snT_hi); SYM(snT_lo, d_snT_lo);
    SYM(fsT_hi, d_fsT_hi); SYM(fsT_lo, d_fsT_lo);
    SYM(thw_hi, d_thw_hi); SYM(thw_lo, d_thw_lo);
    SYM(phw_hi, d_phw_hi); SYM(phw_lo, d_phw_lo);
    SYM(gw_hi,  d_gw_hi);  SYM(gw_lo,  d_gw_lo);
    SYM(Ww_hi,  d_Ww_hi);  SYM(Ww_lo,  d_Ww_lo);
    SYM(thT_hi, d_thT_hi); SYM(thT_lo, d_thT_lo);
    SYM(phT_hi, d_phT_hi); SYM(phT_lo, d_phT_lo);
    SYM(gT_hi,  d_gT_hi);
    SYM(Pp,     d_P);
    SYM(y_hi,   d_y_hi);   SYM(y_lo,   d_y_lo);
    SYM(Gp,     d_G);

    // 1) instance-norm stats
    stats_kernel<<<2 * BB * CC, 256>>>(content, style);
    // 2) normalize + transpose + split (fp16)
    norm_split_T<<<dim3(HWH / 32, CC / 32, 3 * BB), dim3(32, 8)>>>(content, style, fusion);
    // 3) weight splits (fp16)
    weight_split<<<(ICI * CC) / 256, 256>>>((const float*)d_in[3], (const float*)d_in[5],
                                            (const float*)d_in[7], (const float*)d_in[9]);

    // 4) theta_xT : M=4096, N=256, K=512, 3-pass -> split fp16 (limbs feed rescue)
    LAUNCH_GEMM(1, 1, 2, 2, 4, 2, 128, 64, 3,
                xnT_hi, xnT_lo, thw_hi, thw_lo, theta_b, thT_hi, thT_lo,
                HWH, ICI, CC, (long long)HWH * CC, 0LL, (long long)HWH * ICI);

    // 5) phi_sT : 3-pass -> split fp16
    LAUNCH_GEMM(1, 1, 2, 2, 4, 2, 128, 64, 3,
                snT_hi, snT_lo, phw_hi, phw_lo, phi_b, phT_hi, phT_lo,
                HWH, ICI, CC, (long long)HWH * CC, 0LL, (long long)HWH * ICI);

    // 6) g_sT : M=256, N=4096, K=512, 3-pass -> plain fp16 (lo never used)
    LAUNCH_GEMM(1, 1, 3, 1, 4, 2, 128, 64, 3,
                gw_hi, gw_lo, fsT_hi, fsT_lo, g_b, gT_hi, (void*)nullptr,
                ICI, HWH, CC, 0LL, (long long)HWH * CC, (long long)ICI * HWH);

    // 7) G (screening) : M=N=4096, K=256, SINGLE fp16 pass -> fp16 out
    LAUNCH_GEMM(0, 0, 3, 0, 2, 4, 128, 128, 2,
                thT_hi, thT_hi, phT_hi, phT_hi, (const float*)nullptr, Gp, (void*)nullptr,
                HWH, HWH, ICI, (long long)HWH * ICI, (long long)HWH * ICI, (long long)HWH * HWH);

    // 8) softmax: fp16 screening + exact candidate rescue -> P (fp16)
    attn_softmax_kernel<<<dim3(1024, BB), 256>>>(scale);

    // 9) y = P @ g_s : single pass (P fp16 x g_hi fp16), grid 256
    LAUNCH_GEMM(0, 0, 2, 0, 4, 2, 128, 64, 3,
                Pp, Pp, gT_hi, gT_hi, (const float*)nullptr, y_hi, y_lo,
                HWH, ICI, HWH, (long long)HWH * HWH, (long long)ICI * HWH, (long long)HWH * ICI);

    // 10) out = W_w @ y^T + W_b : M=512, N=4096, K=256 -> fp32, 3-pass
    LAUNCH_GEMM(1, 1, 0, 1, 2, 4, 128, 128, 2,
                Ww_hi, Ww_lo, y_hi, y_lo, W_b, out, (void*)nullptr,
                CC, HWH, ICI, 0LL, (long long)HWH * ICI, (long long)CC * HWH);
}